// round 12
// baseline (speedup 1.0000x reference)
#include <cuda_runtime.h>
#include <cuda_fp16.h>
#include <cstdint>
#include <cstddef>

// Problem constants
#define BSZ   2
#define NSEQ  2048
#define DIN   2048
#define DOUT  2048
#define NH    16
#define NG    4
#define HD    128
#define MROWS (BSZ * NSEQ)   // 4096
#define KVDIM (NG * HD)      // 512
#define NQKV  (DOUT + 2 * KVDIM)   // 3072

// ---------------- scratch (no allocations allowed) ----------------
__device__ __align__(16) __half g_q16[MROWS * DOUT];
__device__ __align__(16) __half g_k16[MROWS * KVDIM];
__device__ __align__(16) __half g_v16[MROWS * KVDIM];
__device__ __align__(16) __half g_x16[MROWS * DIN];
__device__ __align__(16) __half g_ctx16[MROWS * DOUT];
__device__ __align__(16) __half g_wqkvt[NQKV * DIN];    // [Wq;Wk;Wv]^T
__device__ __align__(16) __half g_wot[DOUT * DOUT];     // Wo^T

// ---------------- helpers ----------------
__device__ __forceinline__ uint32_t smem_u32(const void* p) {
    uint32_t a;
    asm("{ .reg .u64 t; cvta.to.shared.u64 t, %1; cvt.u32.u64 %0, t; }" : "=r"(a) : "l"(p));
    return a;
}
__device__ __forceinline__ void cp_async16(uint32_t saddr, const void* gaddr) {
    asm volatile("cp.async.cg.shared.global [%0], [%1], 16;" :: "r"(saddr), "l"(gaddr));
}
#define CP_COMMIT() asm volatile("cp.async.commit_group;" ::: "memory")
#define CP_WAIT(n)  asm volatile("cp.async.wait_group %0;" :: "n"(n) : "memory")

__device__ __forceinline__ void ldm_x4(uint32_t& r0, uint32_t& r1, uint32_t& r2, uint32_t& r3,
                                       uint32_t addr) {
    asm volatile("ldmatrix.sync.aligned.m8n8.x4.shared.b16 {%0, %1, %2, %3}, [%4];"
                 : "=r"(r0), "=r"(r1), "=r"(r2), "=r"(r3) : "r"(addr));
}
__device__ __forceinline__ void ldm_x4t(uint32_t& r0, uint32_t& r1, uint32_t& r2, uint32_t& r3,
                                        uint32_t addr) {
    asm volatile("ldmatrix.sync.aligned.m8n8.x4.trans.shared.b16 {%0, %1, %2, %3}, [%4];"
                 : "=r"(r0), "=r"(r1), "=r"(r2), "=r"(r3) : "r"(addr));
}
__device__ __forceinline__ void mma_f16(float* d, const uint32_t* a, const uint32_t* b) {
    asm volatile(
        "mma.sync.aligned.m16n8k16.row.col.f32.f16.f16.f32 "
        "{%0, %1, %2, %3}, {%4, %5, %6, %7}, {%8, %9}, {%0, %1, %2, %3};"
        : "+f"(d[0]), "+f"(d[1]), "+f"(d[2]), "+f"(d[3])
        : "r"(a[0]), "r"(a[1]), "r"(a[2]), "r"(a[3]), "r"(b[0]), "r"(b[1]));
}
__device__ __forceinline__ uint32_t pack_half2(float a, float b) {
    __half2 h = __halves2half2(__float2half_rn(a), __float2half_rn(b));
    return *reinterpret_cast<uint32_t*>(&h);
}

// ---------------- conversion kernels ----------------
__global__ __launch_bounds__(256) void round_fp16_kernel(
    const float* __restrict__ in, __half* __restrict__ out, int n4)
{
    int i = blockIdx.x * 256 + threadIdx.x;
    if (i >= n4) return;
    float4 v = ((const float4*)in)[i];
    ((__half2*)out)[2 * i]     = __halves2half2(__float2half_rn(v.x), __float2half_rn(v.y));
    ((__half2*)out)[2 * i + 1] = __halves2half2(__float2half_rn(v.z), __float2half_rn(v.w));
}

// Fused transpose of Wq/Wk/Wv into g_wqkvt (rows: 0..2047 q, 2048..2559 k, 2560..3071 v)
__global__ __launch_bounds__(256) void transpose_qkv_kernel(
    const float* __restrict__ Wq, const float* __restrict__ Wk,
    const float* __restrict__ Wv, __half* __restrict__ T)
{
    __shared__ float tile[32][33];
    const int bx = blockIdx.x;          // 0..95
    const float* W;
    int n0, rowbase, Nsrc;
    if (bx < 64)      { W = Wq; n0 = bx * 32;        rowbase = 0;    Nsrc = DOUT; }
    else if (bx < 80) { W = Wk; n0 = (bx - 64) * 32; rowbase = 2048; Nsrc = KVDIM; }
    else              { W = Wv; n0 = (bx - 80) * 32; rowbase = 2560; Nsrc = KVDIM; }
    const int k0 = blockIdx.y * 32;
    const int tx = threadIdx.x & 31, ty = threadIdx.x >> 5;
    #pragma unroll
    for (int r = ty; r < 32; r += 8)
        tile[r][tx] = W[(size_t)(k0 + r) * Nsrc + n0 + tx];
    __syncthreads();
    #pragma unroll
    for (int r = ty; r < 32; r += 8)
        T[(size_t)(rowbase + n0 + r) * DIN + k0 + tx] = __float2half_rn(tile[tx][r]);
}

// W[K,N] fp32 -> T[N,K] fp16 single
__global__ __launch_bounds__(256) void transpose_single_kernel(
    const float* __restrict__ W, __half* __restrict__ T, int K, int N)
{
    __shared__ float tile[32][33];
    int k0 = blockIdx.y * 32, n0 = blockIdx.x * 32;
    int tx = threadIdx.x & 31, ty = threadIdx.x >> 5;
    #pragma unroll
    for (int r = ty; r < 32; r += 8)
        tile[r][tx] = W[(size_t)(k0 + r) * N + n0 + tx];
    __syncthreads();
    #pragma unroll
    for (int r = ty; r < 32; r += 8)
        T[(size_t)(n0 + r) * K + k0 + tx] = __float2half_rn(tile[tx][r]);
}

// ---------------- HMMA 1-pass GEMM: 4 warps, 64x64 warp tiles, BK=64, 3-stage, swizzled ----------------
// CTA 128x128, 128 threads (2x2 warps).
// smem tile: 128 rows x 128 B, phys 16B-chunk = c ^ (r & 7)  (conflict-free stores + ldmatrix)
#define GBK       64
#define TILE_B    (128 * 128)              // 16384 B
#define STAGE_B   (2 * TILE_B)             // 32768 B (A, B)
#define NSTAGE    3
#define GEMM_SMEM (NSTAGE * STAGE_B)       // 98304 B

#define SWZ(r, ck) ((uint32_t)(r) * 128u + ((uint32_t)((ck) ^ ((r) & 7)) << 4))

__global__ __launch_bounds__(128, 2) void mma_gemm_kernel(
    const __half* __restrict__ A, const __half* __restrict__ B,
    float* __restrict__ C, const float* __restrict__ bias,
    __half* __restrict__ q16, __half* __restrict__ k16, __half* __restrict__ v16,
    int N, int K)
{
    extern __shared__ char smem[];
    const uint32_t sb = smem_u32(smem);
    const int tid  = threadIdx.x;
    const int wid  = tid >> 5;
    const int lane = tid & 31;
    const int row0 = blockIdx.y * 128;
    const int col0 = blockIdx.x * 128;
    const int wm   = (wid & 1) * 64;       // warp M offset
    const int wn   = (wid >> 1) * 64;      // warp N offset

    float acc[4][8][4];
    #pragma unroll
    for (int i = 0; i < 4; i++)
        #pragma unroll
        for (int j = 0; j < 8; j++)
            #pragma unroll
            for (int r = 0; r < 4; r++) acc[i][j][r] = 0.f;

    const int nch = K / GBK;

    auto load_stage = [&](int ch, int stage) {
        const int k0 = ch * GBK;
        const uint32_t sbase = sb + stage * STAGE_B;
        #pragma unroll
        for (int t = 0; t < 16; t++) {
            int idx = tid + t * 128;            // 0..2047
            int tensor = idx >> 10;             // 0 = A, 1 = B
            int rem = idx & 1023;
            int r = rem >> 3;                   // 0..127
            int c = rem & 7;                    // 16B chunk
            const __half* gp = (tensor == 0)
                ? A + (size_t)(row0 + r) * K + k0 + c * 8
                : B + (size_t)(col0 + r) * K + k0 + c * 8;
            cp_async16(sbase + tensor * TILE_B + SWZ(r, c), gp);
        }
    };

    load_stage(0, 0); CP_COMMIT();
    load_stage(1, 1); CP_COMMIT();

    int stage = 0;
    for (int ch = 0; ch < nch; ch++) {
        if (ch + 1 < nch) { CP_WAIT(1); } else { CP_WAIT(0); }
        __syncthreads();
        if (ch + 2 < nch) {
            int s2 = stage + 2; if (s2 >= NSTAGE) s2 -= NSTAGE;
            load_stage(ch + 2, s2);
            CP_COMMIT();
        }

        const uint32_t sbase = sb + stage * STAGE_B;
        const uint32_t a_t = sbase;
        const uint32_t b_t = sbase + TILE_B;

        #pragma unroll
        for (int ks = 0; ks < 4; ks++) {
            uint32_t fa[4][4];
            #pragma unroll
            for (int mi = 0; mi < 4; mi++) {
                int r = wm + mi * 16 + (lane & 15);
                int ck = ks * 2 + (lane >> 4);
                ldm_x4(fa[mi][0], fa[mi][1], fa[mi][2], fa[mi][3], a_t + SWZ(r, ck));
            }
            uint32_t fb[8][2];
            #pragma unroll
            for (int p = 0; p < 4; p++) {
                int r = wn + p * 16 + (lane >> 4) * 8 + (lane & 7);
                int ck = ks * 2 + ((lane >> 3) & 1);
                uint32_t r0, r1, r2, r3;
                ldm_x4(r0, r1, r2, r3, b_t + SWZ(r, ck));
                fb[2 * p][0] = r0; fb[2 * p][1] = r1;
                fb[2 * p + 1][0] = r2; fb[2 * p + 1][1] = r3;
            }
            #pragma unroll
            for (int mi = 0; mi < 4; mi++)
                #pragma unroll
                for (int ni = 0; ni < 8; ni++)
                    mma_f16(acc[mi][ni], fa[mi], fb[ni]);
        }
        stage++; if (stage >= NSTAGE) stage -= NSTAGE;
    }

    const int qrow = lane >> 2;
    const int qcol = (lane & 3) * 2;
    if (C != nullptr) {
        #pragma unroll
        for (int mi = 0; mi < 4; mi++)
            #pragma unroll
            for (int ni = 0; ni < 8; ni++) {
                int r = row0 + wm + mi * 16 + qrow;
                int c = col0 + wn + ni * 8 + qcol;
                float b0 = 0.f, b1 = 0.f;
                if (bias != nullptr) { b0 = bias[c]; b1 = bias[c + 1]; }
                *(float2*)(C + (size_t)r * N + c) =
                    make_float2(acc[mi][ni][0] + b0, acc[mi][ni][1] + b1);
                *(float2*)(C + (size_t)(r + 8) * N + c) =
                    make_float2(acc[mi][ni][2] + b0, acc[mi][ni][3] + b1);
            }
    } else {
        __half* dst; int nD, c0;
        if (col0 < DOUT)              { dst = q16; nD = DOUT;  c0 = col0; }
        else if (col0 < DOUT + KVDIM) { dst = k16; nD = KVDIM; c0 = col0 - DOUT; }
        else                          { dst = v16; nD = KVDIM; c0 = col0 - DOUT - KVDIM; }
        #pragma unroll
        for (int mi = 0; mi < 4; mi++)
            #pragma unroll
            for (int ni = 0; ni < 8; ni++) {
                int r = row0 + wm + mi * 16 + qrow;
                int c = c0 + wn + ni * 8 + qcol;
                *(uint32_t*)(dst + (size_t)r * nD + c) =
                    pack_half2(acc[mi][ni][0], acc[mi][ni][1]);
                *(uint32_t*)(dst + (size_t)(r + 8) * nD + c) =
                    pack_half2(acc[mi][ni][2], acc[mi][ni][3]);
            }
    }
}

// ---------------- HMMA fp16 causal GQA flash attention (proven round-8 shape) ----------------
// CTA: (b,h) x 64 query rows; 4 warps x 16 rows; key blocks of 64, double-buffered.
#define AROWB 136                          // halfs per padded row (272 B)
#define ATILE (64 * AROWB * 2)             // 17408 B
#define ATTN_SMEM (5 * ATILE)              // 87040 B: Q, K0, V0, K1, V1

__global__ __launch_bounds__(128, 2) void attn6_kernel(
    const __half* __restrict__ Q,
    const __half* __restrict__ K16,
    const __half* __restrict__ V16,
    __half* __restrict__ Cx)
{
    extern __shared__ char smem[];
    const uint32_t sb = smem_u32(smem);
    const int tid  = threadIdx.x;
    const int wid  = tid >> 5;
    const int lane = tid & 31;
    const int b = blockIdx.z;
    const int h = blockIdx.y;
    const int g = h >> 2;
    const int qb = gridDim.x - 1 - blockIdx.x;
    const int q0 = qb * 64;
    const int wrow = wid * 16;

    const uint32_t s_q = sb;
    auto s_k = [&](int buf) { return sb + ATILE + buf * 2 * ATILE; };
    auto s_v = [&](int buf) { return sb + 2 * ATILE + buf * 2 * ATILE; };

    const float scale = 0.08838834764831845f;

    #pragma unroll
    for (int t = 0; t < 8; t++) {
        int idx = tid + t * 128;
        int r = idx >> 4;
        int c = idx & 15;
        size_t go = ((size_t)(b * NSEQ + q0 + r) * NH + h) * HD + c * 8;
        cp_async16(s_q + (uint32_t)r * (AROWB * 2) + c * 16, Q + go);
    }
    CP_COMMIT();

    auto load_kv = [&](int kb, int buf) {
        #pragma unroll
        for (int t = 0; t < 8; t++) {
            int idx = tid + t * 128;
            int r = idx >> 4;
            int c = idx & 15;
            size_t go = ((size_t)(b * NSEQ + kb * 64 + r) * NG + g) * HD + c * 8;
            uint32_t so = (uint32_t)r * (AROWB * 2) + c * 16;
            cp_async16(s_k(buf) + so, K16 + go);
            cp_async16(s_v(buf) + so, V16 + go);
        }
        CP_COMMIT();
    };

    load_kv(0, 0);

    float m0 = -1e30f, m1 = -1e30f, l0 = 0.f, l1 = 0.f;
    float o[16][4];
    #pragma unroll
    for (int n = 0; n < 16; n++)
        #pragma unroll
        for (int r = 0; r < 4; r++) o[n][r] = 0.f;

    for (int kb = 0; kb <= qb; kb++) {
        const int cur = kb & 1;
        __syncthreads();
        if (kb < qb) {
            load_kv(kb + 1, 1 - cur);
            CP_WAIT(1);
        } else {
            CP_WAIT(0);
        }
        __syncthreads();

        const uint32_t sk = s_k(cur), sv = s_v(cur);

        float sacc[8][4];
        #pragma unroll
        for (int j = 0; j < 8; j++)
            #pragma unroll
            for (int r = 0; r < 4; r++) sacc[j][r] = 0.f;

        #pragma unroll
        for (int kc = 0; kc < 8; kc++) {
            uint32_t aoff = (uint32_t)(wrow + (lane & 15)) * (AROWB * 2)
                          + kc * 32 + (lane >> 4) * 16;
            uint32_t fa[4];
            ldm_x4(fa[0], fa[1], fa[2], fa[3], s_q + aoff);
            uint32_t fb[8][2];
            #pragma unroll
            for (int p = 0; p < 4; p++) {
                uint32_t boff = (uint32_t)(p * 16 + (lane >> 4) * 8 + (lane & 7)) * (AROWB * 2)
                              + kc * 32 + ((lane >> 3) & 1) * 16;
                uint32_t r0, r1, r2, r3;
                ldm_x4(r0, r1, r2, r3, sk + boff);
                fb[2 * p][0] = r0; fb[2 * p][1] = r1;
                fb[2 * p + 1][0] = r2; fb[2 * p + 1][1] = r3;
            }
            #pragma unroll
            for (int j = 0; j < 8; j++)
                mma_f16(sacc[j], fa, fb[j]);
        }

        const bool diag = (kb == qb);
        const int qr0 = q0 + wrow + (lane >> 2);
        float mb0 = -1e30f, mb1 = -1e30f;
        #pragma unroll
        for (int j = 0; j < 8; j++) {
            #pragma unroll
            for (int r = 0; r < 4; r++) sacc[j][r] *= scale;
            if (diag) {
                int key = kb * 64 + j * 8 + (lane & 3) * 2;
                if (key     > qr0)     sacc[j][0] = -1e30f;
                if (key + 1 > qr0)     sacc[j][1] = -1e30f;
                if (key     > qr0 + 8) sacc[j][2] = -1e30f;
                if (key + 1 > qr0 + 8) sacc[j][3] = -1e30f;
            }
            mb0 = fmaxf(mb0, fmaxf(sacc[j][0], sacc[j][1]));
            mb1 = fmaxf(mb1, fmaxf(sacc[j][2], sacc[j][3]));
        }
        mb0 = fmaxf(mb0, __shfl_xor_sync(0xFFFFFFFFu, mb0, 1));
        mb0 = fmaxf(mb0, __shfl_xor_sync(0xFFFFFFFFu, mb0, 2));
        mb1 = fmaxf(mb1, __shfl_xor_sync(0xFFFFFFFFu, mb1, 1));
        mb1 = fmaxf(mb1, __shfl_xor_sync(0xFFFFFFFFu, mb1, 2));

        float mn0 = fmaxf(m0, mb0), mn1 = fmaxf(m1, mb1);
        float a0 = __expf(m0 - mn0), a1 = __expf(m1 - mn1);
        m0 = mn0; m1 = mn1;

        float s0 = 0.f, s1 = 0.f;
        uint32_t pa[4][4];
        #pragma unroll
        for (int j = 0; j < 8; j++) {
            float p0 = __expf(sacc[j][0] - mn0);
            float p1 = __expf(sacc[j][1] - mn0);
            float p2 = __expf(sacc[j][2] - mn1);
            float p3 = __expf(sacc[j][3] - mn1);
            s0 += p0 + p1;
            s1 += p2 + p3;
            int t = j >> 1, w = (j & 1) * 2;
            pa[t][0 + w] = pack_half2(p0, p1);
            pa[t][1 + w] = pack_half2(p2, p3);
        }
        s0 += __shfl_xor_sync(0xFFFFFFFFu, s0, 1);
        s0 += __shfl_xor_sync(0xFFFFFFFFu, s0, 2);
        s1 += __shfl_xor_sync(0xFFFFFFFFu, s1, 1);
        s1 += __shfl_xor_sync(0xFFFFFFFFu, s1, 2);
        l0 = l0 * a0 + s0;
        l1 = l1 * a1 + s1;

        #pragma unroll
        for (int n = 0; n < 16; n++) {
            o[n][0] *= a0; o[n][1] *= a0;
            o[n][2] *= a1; o[n][3] *= a1;
        }

        #pragma unroll
        for (int np = 0; np < 8; np++) {
            #pragma unroll
            for (int t = 0; t < 4; t++) {
                uint32_t vaddr = (uint32_t)(16 * t + (lane & 7) + ((lane >> 3) & 1) * 8) * (AROWB * 2)
                               + (np * 16 + (lane >> 4) * 8) * 2;
                uint32_t h0, h1, h2, h3;
                ldm_x4t(h0, h1, h2, h3, sv + vaddr);
                uint32_t bh0[2] = {h0, h1}, bh1[2] = {h2, h3};
                mma_f16(o[2 * np],     pa[t], bh0);
                mma_f16(o[2 * np + 1], pa[t], bh1);
            }
        }
    }

    const float inv0 = 1.f / l0, inv1 = 1.f / l1;
    const int r0g = q0 + wrow + (lane >> 2);
    const int r1g = r0g + 8;
    #pragma unroll
    for (int n = 0; n < 16; n++) {
        int d = n * 8 + (lane & 3) * 2;
        size_t off0 = ((size_t)(b * NSEQ + r0g) * NH + h) * HD + d;
        size_t off1 = ((size_t)(b * NSEQ + r1g) * NH + h) * HD + d;
        *(uint32_t*)(Cx + off0) = pack_half2(o[n][0] * inv0, o[n][1] * inv0);
        *(uint32_t*)(Cx + off1) = pack_half2(o[n][2] * inv1, o[n][3] * inv1);
    }
}

// ---------------- launch ----------------
extern "C" void kernel_launch(void* const* d_in, const int* in_sizes, int n_in,
                              void* d_out, int out_size)
{
    const float* x  = (const float*)d_in[0];
    const float* Wq = (const float*)d_in[1];
    const float* Wk = (const float*)d_in[2];
    const float* Wv = (const float*)d_in[3];
    const float* Wo = (const float*)d_in[4];
    const float* bo = (const float*)d_in[5];
    float* out = (float*)d_out;

    __half *q16, *k16, *v16, *x16, *ctx16, *wqkvt, *wot;
    cudaGetSymbolAddress((void**)&q16,   g_q16);
    cudaGetSymbolAddress((void**)&k16,   g_k16);
    cudaGetSymbolAddress((void**)&v16,   g_v16);
    cudaGetSymbolAddress((void**)&x16,   g_x16);
    cudaGetSymbolAddress((void**)&ctx16, g_ctx16);
    cudaGetSymbolAddress((void**)&wqkvt, g_wqkvt);
    cudaGetSymbolAddress((void**)&wot,   g_wot);

    static bool attrs_set = false;
    if (!attrs_set) {
        cudaFuncSetAttribute(mma_gemm_kernel, cudaFuncAttributeMaxDynamicSharedMemorySize,
                             GEMM_SMEM);
        cudaFuncSetAttribute(attn6_kernel, cudaFuncAttributeMaxDynamicSharedMemorySize,
                             ATTN_SMEM);
        attrs_set = true;
    }

    dim3 blk(256);

    // conversions
    round_fp16_kernel<<<(MROWS * DIN / 4 + 255) / 256, blk>>>(x, x16, MROWS * DIN / 4);
    transpose_qkv_kernel<<<dim3(96, DIN / 32), blk>>>(Wq, Wk, Wv, wqkvt);
    transpose_single_kernel<<<dim3(DOUT / 32, DOUT / 32), blk>>>(Wo, wot, DOUT, DOUT);

    // fused QKV projection (fp16 outputs, routed by column)
    mma_gemm_kernel<<<dim3(NQKV / 128, MROWS / 128), dim3(128), GEMM_SMEM>>>(
        x16, wqkvt, nullptr, nullptr, q16, k16, v16, NQKV, DIN);

    // attention (fp16 ctx output)
    attn6_kernel<<<dim3(NSEQ / 64, NH, BSZ), dim3(128), ATTN_SMEM>>>(
        q16, k16, v16, ctx16);

    // output projection (1-pass, fp32 + bias)
    mma_gemm_kernel<<<dim3(DOUT / 128, MROWS / 128), dim3(128), GEMM_SMEM>>>(
        ctx16, wot, out, bo, nullptr, nullptr, nullptr, DOUT, DOUT);
}

// round 13
// speedup vs baseline: 1.5248x; 1.5248x over previous
#include <cuda_runtime.h>
#include <cuda_fp16.h>
#include <cstdint>
#include <cstddef>

// Problem constants
#define BSZ   2
#define NSEQ  2048
#define DIN   2048
#define DOUT  2048
#define NH    16
#define NG    4
#define HD    128
#define MROWS (BSZ * NSEQ)   // 4096
#define KVDIM (NG * HD)      // 512
#define NQKV  (DOUT + 2 * KVDIM)   // 3072

// ---------------- scratch (no allocations allowed) ----------------
__device__ __align__(16) __half g_q16[MROWS * DOUT];
__device__ __align__(16) __half g_k16[MROWS * KVDIM];
__device__ __align__(16) __half g_v16[MROWS * KVDIM];
__device__ __align__(16) __half g_x16[MROWS * DIN];
__device__ __align__(16) __half g_ctx16[MROWS * DOUT];
__device__ __align__(16) __half g_wqkvt[NQKV * DIN];    // [Wq;Wk;Wv]^T
__device__ __align__(16) __half g_wot[DOUT * DOUT];     // Wo^T

// ---------------- helpers ----------------
__device__ __forceinline__ uint32_t smem_u32(const void* p) {
    uint32_t a;
    asm("{ .reg .u64 t; cvta.to.shared.u64 t, %1; cvt.u32.u64 %0, t; }" : "=r"(a) : "l"(p));
    return a;
}
__device__ __forceinline__ void cp_async16(uint32_t saddr, const void* gaddr) {
    asm volatile("cp.async.cg.shared.global [%0], [%1], 16;" :: "r"(saddr), "l"(gaddr));
}
#define CP_COMMIT() asm volatile("cp.async.commit_group;" ::: "memory")
#define CP_WAIT(n)  asm volatile("cp.async.wait_group %0;" :: "n"(n) : "memory")

__device__ __forceinline__ void ldm_x4(uint32_t& r0, uint32_t& r1, uint32_t& r2, uint32_t& r3,
                                       uint32_t addr) {
    asm volatile("ldmatrix.sync.aligned.m8n8.x4.shared.b16 {%0, %1, %2, %3}, [%4];"
                 : "=r"(r0), "=r"(r1), "=r"(r2), "=r"(r3) : "r"(addr));
}
__device__ __forceinline__ void ldm_x4t(uint32_t& r0, uint32_t& r1, uint32_t& r2, uint32_t& r3,
                                        uint32_t addr) {
    asm volatile("ldmatrix.sync.aligned.m8n8.x4.trans.shared.b16 {%0, %1, %2, %3}, [%4];"
                 : "=r"(r0), "=r"(r1), "=r"(r2), "=r"(r3) : "r"(addr));
}
__device__ __forceinline__ void mma_f16(float* d, const uint32_t* a, const uint32_t* b) {
    asm volatile(
        "mma.sync.aligned.m16n8k16.row.col.f32.f16.f16.f32 "
        "{%0, %1, %2, %3}, {%4, %5, %6, %7}, {%8, %9}, {%0, %1, %2, %3};"
        : "+f"(d[0]), "+f"(d[1]), "+f"(d[2]), "+f"(d[3])
        : "r"(a[0]), "r"(a[1]), "r"(a[2]), "r"(a[3]), "r"(b[0]), "r"(b[1]));
}
__device__ __forceinline__ uint32_t pack_half2(float a, float b) {
    __half2 h = __halves2half2(__float2half_rn(a), __float2half_rn(b));
    return *reinterpret_cast<uint32_t*>(&h);
}

// ---------------- conversion kernels ----------------
__global__ __launch_bounds__(256) void round_fp16_kernel(
    const float* __restrict__ in, __half* __restrict__ out, int n4)
{
    int i = blockIdx.x * 256 + threadIdx.x;
    if (i >= n4) return;
    float4 v = ((const float4*)in)[i];
    ((__half2*)out)[2 * i]     = __halves2half2(__float2half_rn(v.x), __float2half_rn(v.y));
    ((__half2*)out)[2 * i + 1] = __halves2half2(__float2half_rn(v.z), __float2half_rn(v.w));
}

// Fused transpose of Wq/Wk/Wv into g_wqkvt (rows: 0..2047 q, 2048..2559 k, 2560..3071 v)
__global__ __launch_bounds__(256) void transpose_qkv_kernel(
    const float* __restrict__ Wq, const float* __restrict__ Wk,
    const float* __restrict__ Wv, __half* __restrict__ T)
{
    __shared__ float tile[32][33];
    const int bx = blockIdx.x;          // 0..95
    const float* W;
    int n0, rowbase, Nsrc;
    if (bx < 64)      { W = Wq; n0 = bx * 32;        rowbase = 0;    Nsrc = DOUT; }
    else if (bx < 80) { W = Wk; n0 = (bx - 64) * 32; rowbase = 2048; Nsrc = KVDIM; }
    else              { W = Wv; n0 = (bx - 80) * 32; rowbase = 2560; Nsrc = KVDIM; }
    const int k0 = blockIdx.y * 32;
    const int tx = threadIdx.x & 31, ty = threadIdx.x >> 5;
    #pragma unroll
    for (int r = ty; r < 32; r += 8)
        tile[r][tx] = W[(size_t)(k0 + r) * Nsrc + n0 + tx];
    __syncthreads();
    #pragma unroll
    for (int r = ty; r < 32; r += 8)
        T[(size_t)(rowbase + n0 + r) * DIN + k0 + tx] = __float2half_rn(tile[tx][r]);
}

// W[K,N] fp32 -> T[N,K] fp16 single
__global__ __launch_bounds__(256) void transpose_single_kernel(
    const float* __restrict__ W, __half* __restrict__ T, int K, int N)
{
    __shared__ float tile[32][33];
    int k0 = blockIdx.y * 32, n0 = blockIdx.x * 32;
    int tx = threadIdx.x & 31, ty = threadIdx.x >> 5;
    #pragma unroll
    for (int r = ty; r < 32; r += 8)
        tile[r][tx] = W[(size_t)(k0 + r) * N + n0 + tx];
    __syncthreads();
    #pragma unroll
    for (int r = ty; r < 32; r += 8)
        T[(size_t)(n0 + r) * K + k0 + tx] = __float2half_rn(tile[tx][r]);
}

// ---------------- HMMA 1-pass GEMM: 4 warps, 64x64 warp tiles, BK=32, 3-stage, swizzled ----------------
// (exact round-11 configuration — empirically optimal)
#define GBK       32
#define TILE_B    (128 * 64)               // 8192 B
#define STAGE_B   (2 * TILE_B)             // 16384 B (A, B)
#define NSTAGE    3
#define GEMM_SMEM (NSTAGE * STAGE_B)       // 49152 B

#define SWZ(r, ck) ((uint32_t)(r) * 64u + ((uint32_t)((ck) ^ (((r) >> 1) & 3)) << 4))

__global__ __launch_bounds__(128, 2) void mma_gemm_kernel(
    const __half* __restrict__ A, const __half* __restrict__ B,
    float* __restrict__ C, const float* __restrict__ bias,
    __half* __restrict__ q16, __half* __restrict__ k16, __half* __restrict__ v16,
    int N, int K)
{
    extern __shared__ char smem[];
    const uint32_t sb = smem_u32(smem);
    const int tid  = threadIdx.x;
    const int wid  = tid >> 5;
    const int lane = tid & 31;
    const int row0 = blockIdx.y * 128;
    const int col0 = blockIdx.x * 128;
    const int wm   = (wid & 1) * 64;       // warp M offset
    const int wn   = (wid >> 1) * 64;      // warp N offset

    float acc[4][8][4];
    #pragma unroll
    for (int i = 0; i < 4; i++)
        #pragma unroll
        for (int j = 0; j < 8; j++)
            #pragma unroll
            for (int r = 0; r < 4; r++) acc[i][j][r] = 0.f;

    const int nch = K / GBK;

    auto load_stage = [&](int ch, int stage) {
        const int k0 = ch * GBK;
        const uint32_t sbase = sb + stage * STAGE_B;
        #pragma unroll
        for (int t = 0; t < 8; t++) {
            int idx = tid + t * 128;            // 0..1023
            int tensor = idx >> 9;              // 0 = A, 1 = B
            int rem = idx & 511;
            int r = rem >> 2;
            int c = rem & 3;
            const __half* gp = (tensor == 0)
                ? A + (size_t)(row0 + r) * K + k0 + c * 8
                : B + (size_t)(col0 + r) * K + k0 + c * 8;
            cp_async16(sbase + tensor * TILE_B + SWZ(r, c), gp);
        }
    };

    load_stage(0, 0); CP_COMMIT();
    load_stage(1, 1); CP_COMMIT();

    int stage = 0;
    for (int ch = 0; ch < nch; ch++) {
        if (ch + 1 < nch) { CP_WAIT(1); } else { CP_WAIT(0); }
        __syncthreads();
        if (ch + 2 < nch) {
            int s2 = stage + 2; if (s2 >= NSTAGE) s2 -= NSTAGE;
            load_stage(ch + 2, s2);
            CP_COMMIT();
        }

        const uint32_t sbase = sb + stage * STAGE_B;
        const uint32_t a_t = sbase;
        const uint32_t b_t = sbase + TILE_B;

        #pragma unroll
        for (int ks = 0; ks < 2; ks++) {
            uint32_t fa[4][4];
            #pragma unroll
            for (int mi = 0; mi < 4; mi++) {
                int r = wm + mi * 16 + (lane & 15);
                int ck = ks * 2 + (lane >> 4);
                ldm_x4(fa[mi][0], fa[mi][1], fa[mi][2], fa[mi][3], a_t + SWZ(r, ck));
            }
            uint32_t fb[8][2];
            #pragma unroll
            for (int p = 0; p < 4; p++) {
                int r = wn + p * 16 + (lane >> 4) * 8 + (lane & 7);
                int ck = ks * 2 + ((lane >> 3) & 1);
                uint32_t r0, r1, r2, r3;
                ldm_x4(r0, r1, r2, r3, b_t + SWZ(r, ck));
                fb[2 * p][0] = r0; fb[2 * p][1] = r1;
                fb[2 * p + 1][0] = r2; fb[2 * p + 1][1] = r3;
            }
            #pragma unroll
            for (int mi = 0; mi < 4; mi++)
                #pragma unroll
                for (int ni = 0; ni < 8; ni++)
                    mma_f16(acc[mi][ni], fa[mi], fb[ni]);
        }
        stage++; if (stage >= NSTAGE) stage -= NSTAGE;
    }

    const int qrow = lane >> 2;
    const int qcol = (lane & 3) * 2;
    if (C != nullptr) {
        #pragma unroll
        for (int mi = 0; mi < 4; mi++)
            #pragma unroll
            for (int ni = 0; ni < 8; ni++) {
                int r = row0 + wm + mi * 16 + qrow;
                int c = col0 + wn + ni * 8 + qcol;
                float b0 = 0.f, b1 = 0.f;
                if (bias != nullptr) { b0 = bias[c]; b1 = bias[c + 1]; }
                *(float2*)(C + (size_t)r * N + c) =
                    make_float2(acc[mi][ni][0] + b0, acc[mi][ni][1] + b1);
                *(float2*)(C + (size_t)(r + 8) * N + c) =
                    make_float2(acc[mi][ni][2] + b0, acc[mi][ni][3] + b1);
            }
    } else {
        __half* dst; int nD, c0;
        if (col0 < DOUT)              { dst = q16; nD = DOUT;  c0 = col0; }
        else if (col0 < DOUT + KVDIM) { dst = k16; nD = KVDIM; c0 = col0 - DOUT; }
        else                          { dst = v16; nD = KVDIM; c0 = col0 - DOUT - KVDIM; }
        #pragma unroll
        for (int mi = 0; mi < 4; mi++)
            #pragma unroll
            for (int ni = 0; ni < 8; ni++) {
                int r = row0 + wm + mi * 16 + qrow;
                int c = c0 + wn + ni * 8 + qcol;
                *(uint32_t*)(dst + (size_t)r * nD + c) =
                    pack_half2(acc[mi][ni][0], acc[mi][ni][1]);
                *(uint32_t*)(dst + (size_t)(r + 8) * nD + c) =
                    pack_half2(acc[mi][ni][2], acc[mi][ni][3]);
            }
    }
}

// ---------------- HMMA fp16 causal GQA flash attention ----------------
// CTA: (b,h) x 64 query rows; 4 warps x 16 rows; key blocks of 64, double-buffered.
// Single-sync pipeline: wait(0) -> sync -> issue(kb+1) -> compute(kb).
#define AROWB 136                          // halfs per padded row (272 B)
#define ATILE (64 * AROWB * 2)             // 17408 B
#define ATTN_SMEM (5 * ATILE)              // 87040 B: Q, K0, V0, K1, V1

__global__ __launch_bounds__(128, 2) void attn6_kernel(
    const __half* __restrict__ Q,
    const __half* __restrict__ K16,
    const __half* __restrict__ V16,
    __half* __restrict__ Cx)
{
    extern __shared__ char smem[];
    const uint32_t sb = smem_u32(smem);
    const int tid  = threadIdx.x;
    const int wid  = tid >> 5;
    const int lane = tid & 31;
    const int b = blockIdx.z;
    const int h = blockIdx.y;
    const int g = h >> 2;
    const int qb = gridDim.x - 1 - blockIdx.x;
    const int q0 = qb * 64;
    const int wrow = wid * 16;

    const uint32_t s_q = sb;
    auto s_k = [&](int buf) { return sb + ATILE + buf * 2 * ATILE; };
    auto s_v = [&](int buf) { return sb + 2 * ATILE + buf * 2 * ATILE; };

    const float scale = 0.08838834764831845f;

    #pragma unroll
    for (int t = 0; t < 8; t++) {
        int idx = tid + t * 128;
        int r = idx >> 4;
        int c = idx & 15;
        size_t go = ((size_t)(b * NSEQ + q0 + r) * NH + h) * HD + c * 8;
        cp_async16(s_q + (uint32_t)r * (AROWB * 2) + c * 16, Q + go);
    }

    auto load_kv = [&](int kb, int buf) {
        #pragma unroll
        for (int t = 0; t < 8; t++) {
            int idx = tid + t * 128;
            int r = idx >> 4;
            int c = idx & 15;
            size_t go = ((size_t)(b * NSEQ + kb * 64 + r) * NG + g) * HD + c * 8;
            uint32_t so = (uint32_t)r * (AROWB * 2) + c * 16;
            cp_async16(s_k(buf) + so, K16 + go);
            cp_async16(s_v(buf) + so, V16 + go);
        }
        CP_COMMIT();
    };

    load_kv(0, 0);   // Q rides in this group too

    float m0 = -1e30f, m1 = -1e30f, l0 = 0.f, l1 = 0.f;
    float o[16][4];
    #pragma unroll
    for (int n = 0; n < 16; n++)
        #pragma unroll
        for (int r = 0; r < 4; r++) o[n][r] = 0.f;

    for (int kb = 0; kb <= qb; kb++) {
        const int cur = kb & 1;
        CP_WAIT(0);          // kv(kb) (+Q on first iter) complete
        __syncthreads();     // visibility + all warps past compute of kb-1
        if (kb < qb) load_kv(kb + 1, 1 - cur);   // overwrites buffer consumed at kb-1

        const uint32_t sk = s_k(cur), sv = s_v(cur);

        float sacc[8][4];
        #pragma unroll
        for (int j = 0; j < 8; j++)
            #pragma unroll
            for (int r = 0; r < 4; r++) sacc[j][r] = 0.f;

        #pragma unroll
        for (int kc = 0; kc < 8; kc++) {
            uint32_t aoff = (uint32_t)(wrow + (lane & 15)) * (AROWB * 2)
                          + kc * 32 + (lane >> 4) * 16;
            uint32_t fa[4];
            ldm_x4(fa[0], fa[1], fa[2], fa[3], s_q + aoff);
            uint32_t fb[8][2];
            #pragma unroll
            for (int p = 0; p < 4; p++) {
                uint32_t boff = (uint32_t)(p * 16 + (lane >> 4) * 8 + (lane & 7)) * (AROWB * 2)
                              + kc * 32 + ((lane >> 3) & 1) * 16;
                uint32_t r0, r1, r2, r3;
                ldm_x4(r0, r1, r2, r3, sk + boff);
                fb[2 * p][0] = r0; fb[2 * p][1] = r1;
                fb[2 * p + 1][0] = r2; fb[2 * p + 1][1] = r3;
            }
            #pragma unroll
            for (int j = 0; j < 8; j++)
                mma_f16(sacc[j], fa, fb[j]);
        }

        const bool diag = (kb == qb);
        const int qr0 = q0 + wrow + (lane >> 2);
        float mb0 = -1e30f, mb1 = -1e30f;
        #pragma unroll
        for (int j = 0; j < 8; j++) {
            #pragma unroll
            for (int r = 0; r < 4; r++) sacc[j][r] *= scale;
            if (diag) {
                int key = kb * 64 + j * 8 + (lane & 3) * 2;
                if (key     > qr0)     sacc[j][0] = -1e30f;
                if (key + 1 > qr0)     sacc[j][1] = -1e30f;
                if (key     > qr0 + 8) sacc[j][2] = -1e30f;
                if (key + 1 > qr0 + 8) sacc[j][3] = -1e30f;
            }
            mb0 = fmaxf(mb0, fmaxf(sacc[j][0], sacc[j][1]));
            mb1 = fmaxf(mb1, fmaxf(sacc[j][2], sacc[j][3]));
        }
        mb0 = fmaxf(mb0, __shfl_xor_sync(0xFFFFFFFFu, mb0, 1));
        mb0 = fmaxf(mb0, __shfl_xor_sync(0xFFFFFFFFu, mb0, 2));
        mb1 = fmaxf(mb1, __shfl_xor_sync(0xFFFFFFFFu, mb1, 1));
        mb1 = fmaxf(mb1, __shfl_xor_sync(0xFFFFFFFFu, mb1, 2));

        float mn0 = fmaxf(m0, mb0), mn1 = fmaxf(m1, mb1);
        float a0 = __expf(m0 - mn0), a1 = __expf(m1 - mn1);
        m0 = mn0; m1 = mn1;

        float s0 = 0.f, s1 = 0.f;
        uint32_t pa[4][4];
        #pragma unroll
        for (int j = 0; j < 8; j++) {
            float p0 = __expf(sacc[j][0] - mn0);
            float p1 = __expf(sacc[j][1] - mn0);
            float p2 = __expf(sacc[j][2] - mn1);
            float p3 = __expf(sacc[j][3] - mn1);
            s0 += p0 + p1;
            s1 += p2 + p3;
            int t = j >> 1, w = (j & 1) * 2;
            pa[t][0 + w] = pack_half2(p0, p1);
            pa[t][1 + w] = pack_half2(p2, p3);
        }
        s0 += __shfl_xor_sync(0xFFFFFFFFu, s0, 1);
        s0 += __shfl_xor_sync(0xFFFFFFFFu, s0, 2);
        s1 += __shfl_xor_sync(0xFFFFFFFFu, s1, 1);
        s1 += __shfl_xor_sync(0xFFFFFFFFu, s1, 2);
        l0 = l0 * a0 + s0;
        l1 = l1 * a1 + s1;

        #pragma unroll
        for (int n = 0; n < 16; n++) {
            o[n][0] *= a0; o[n][1] *= a0;
            o[n][2] *= a1; o[n][3] *= a1;
        }

        #pragma unroll
        for (int np = 0; np < 8; np++) {
            #pragma unroll
            for (int t = 0; t < 4; t++) {
                uint32_t vaddr = (uint32_t)(16 * t + (lane & 7) + ((lane >> 3) & 1) * 8) * (AROWB * 2)
                               + (np * 16 + (lane >> 4) * 8) * 2;
                uint32_t h0, h1, h2, h3;
                ldm_x4t(h0, h1, h2, h3, sv + vaddr);
                uint32_t bh0[2] = {h0, h1}, bh1[2] = {h2, h3};
                mma_f16(o[2 * np],     pa[t], bh0);
                mma_f16(o[2 * np + 1], pa[t], bh1);
            }
        }
    }

    const float inv0 = 1.f / l0, inv1 = 1.f / l1;
    const int r0g = q0 + wrow + (lane >> 2);
    const int r1g = r0g + 8;
    #pragma unroll
    for (int n = 0; n < 16; n++) {
        int d = n * 8 + (lane & 3) * 2;
        size_t off0 = ((size_t)(b * NSEQ + r0g) * NH + h) * HD + d;
        size_t off1 = ((size_t)(b * NSEQ + r1g) * NH + h) * HD + d;
        *(uint32_t*)(Cx + off0) = pack_half2(o[n][0] * inv0, o[n][1] * inv0);
        *(uint32_t*)(Cx + off1) = pack_half2(o[n][2] * inv1, o[n][3] * inv1);
    }
}

// ---------------- launch ----------------
extern "C" void kernel_launch(void* const* d_in, const int* in_sizes, int n_in,
                              void* d_out, int out_size)
{
    const float* x  = (const float*)d_in[0];
    const float* Wq = (const float*)d_in[1];
    const float* Wk = (const float*)d_in[2];
    const float* Wv = (const float*)d_in[3];
    const float* Wo = (const float*)d_in[4];
    const float* bo = (const float*)d_in[5];
    float* out = (float*)d_out;

    __half *q16, *k16, *v16, *x16, *ctx16, *wqkvt, *wot;
    cudaGetSymbolAddress((void**)&q16,   g_q16);
    cudaGetSymbolAddress((void**)&k16,   g_k16);
    cudaGetSymbolAddress((void**)&v16,   g_v16);
    cudaGetSymbolAddress((void**)&x16,   g_x16);
    cudaGetSymbolAddress((void**)&ctx16, g_ctx16);
    cudaGetSymbolAddress((void**)&wqkvt, g_wqkvt);
    cudaGetSymbolAddress((void**)&wot,   g_wot);

    static bool attrs_set = false;
    if (!attrs_set) {
        cudaFuncSetAttribute(mma_gemm_kernel, cudaFuncAttributeMaxDynamicSharedMemorySize,
                             GEMM_SMEM);
        cudaFuncSetAttribute(attn6_kernel, cudaFuncAttributeMaxDynamicSharedMemorySize,
                             ATTN_SMEM);
        attrs_set = true;
    }

    dim3 blk(256);

    // conversions
    round_fp16_kernel<<<(MROWS * DIN / 4 + 255) / 256, blk>>>(x, x16, MROWS * DIN / 4);
    transpose_qkv_kernel<<<dim3(96, DIN / 32), blk>>>(Wq, Wk, Wv, wqkvt);
    transpose_single_kernel<<<dim3(DOUT / 32, DOUT / 32), blk>>>(Wo, wot, DOUT, DOUT);

    // fused QKV projection (fp16 outputs, routed by column)
    mma_gemm_kernel<<<dim3(NQKV / 128, MROWS / 128), dim3(128), GEMM_SMEM>>>(
        x16, wqkvt, nullptr, nullptr, q16, k16, v16, NQKV, DIN);

    // attention (fp16 ctx output)
    attn6_kernel<<<dim3(NSEQ / 64, NH, BSZ), dim3(128), ATTN_SMEM>>>(
        q16, k16, v16, ctx16);

    // output projection (1-pass, fp32 + bias)
    mma_gemm_kernel<<<dim3(DOUT / 128, MROWS / 128), dim3(128), GEMM_SMEM>>>(
        ctx16, wot, out, bo, nullptr, nullptr, nullptr, DOUT, DOUT);
}

// round 14
// speedup vs baseline: 1.5359x; 1.0073x over previous
#include <cuda_runtime.h>
#include <cuda_fp16.h>
#include <cstdint>
#include <cstddef>

// Problem constants
#define BSZ   2
#define NSEQ  2048
#define DIN   2048
#define DOUT  2048
#define NH    16
#define NG    4
#define HD    128
#define MROWS (BSZ * NSEQ)   // 4096
#define KVDIM (NG * HD)      // 512
#define NQKV  (DOUT + 2 * KVDIM)   // 3072

// ---------------- scratch (no allocations allowed) ----------------
__device__ __align__(16) __half g_q16[MROWS * DOUT];
__device__ __align__(16) __half g_k16[MROWS * KVDIM];
__device__ __align__(16) __half g_v16[MROWS * KVDIM];
__device__ __align__(16) __half g_x16[MROWS * DIN];
__device__ __align__(16) __half g_ctx16[MROWS * DOUT];
__device__ __align__(16) __half g_wqkvt[NQKV * DIN];    // [Wq*scale;Wk;Wv]^T
__device__ __align__(16) __half g_wot[DOUT * DOUT];     // Wo^T

// ---------------- helpers ----------------
__device__ __forceinline__ uint32_t smem_u32(const void* p) {
    uint32_t a;
    asm("{ .reg .u64 t; cvta.to.shared.u64 t, %1; cvt.u32.u64 %0, t; }" : "=r"(a) : "l"(p));
    return a;
}
__device__ __forceinline__ void cp_async16(uint32_t saddr, const void* gaddr) {
    asm volatile("cp.async.cg.shared.global [%0], [%1], 16;" :: "r"(saddr), "l"(gaddr));
}
#define CP_COMMIT() asm volatile("cp.async.commit_group;" ::: "memory")
#define CP_WAIT(n)  asm volatile("cp.async.wait_group %0;" :: "n"(n) : "memory")

__device__ __forceinline__ void ldm_x4(uint32_t& r0, uint32_t& r1, uint32_t& r2, uint32_t& r3,
                                       uint32_t addr) {
    asm volatile("ldmatrix.sync.aligned.m8n8.x4.shared.b16 {%0, %1, %2, %3}, [%4];"
                 : "=r"(r0), "=r"(r1), "=r"(r2), "=r"(r3) : "r"(addr));
}
__device__ __forceinline__ void ldm_x4t(uint32_t& r0, uint32_t& r1, uint32_t& r2, uint32_t& r3,
                                        uint32_t addr) {
    asm volatile("ldmatrix.sync.aligned.m8n8.x4.trans.shared.b16 {%0, %1, %2, %3}, [%4];"
                 : "=r"(r0), "=r"(r1), "=r"(r2), "=r"(r3) : "r"(addr));
}
__device__ __forceinline__ void mma_f16(float* d, const uint32_t* a, const uint32_t* b) {
    asm volatile(
        "mma.sync.aligned.m16n8k16.row.col.f32.f16.f16.f32 "
        "{%0, %1, %2, %3}, {%4, %5, %6, %7}, {%8, %9}, {%0, %1, %2, %3};"
        : "+f"(d[0]), "+f"(d[1]), "+f"(d[2]), "+f"(d[3])
        : "r"(a[0]), "r"(a[1]), "r"(a[2]), "r"(a[3]), "r"(b[0]), "r"(b[1]));
}
__device__ __forceinline__ uint32_t pack_half2(float a, float b) {
    __half2 h = __halves2half2(__float2half_rn(a), __float2half_rn(b));
    return *reinterpret_cast<uint32_t*>(&h);
}

// ---------------- conversion kernels ----------------
__global__ __launch_bounds__(256) void round_fp16_kernel(
    const float* __restrict__ in, __half* __restrict__ out, int n4)
{
    int i = blockIdx.x * 256 + threadIdx.x;
    if (i >= n4) return;
    float4 v = ((const float4*)in)[i];
    ((__half2*)out)[2 * i]     = __halves2half2(__float2half_rn(v.x), __float2half_rn(v.y));
    ((__half2*)out)[2 * i + 1] = __halves2half2(__float2half_rn(v.z), __float2half_rn(v.w));
}

// Fused transpose of Wq(*scale)/Wk/Wv/Wo.
// grid.x 0..63: Wq -> wqkvt rows 0..2047 (scaled)
//        64..79: Wk -> rows 2048..2559
//        80..95: Wv -> rows 2560..3071
//        96..159: Wo -> wot
__global__ __launch_bounds__(256) void transpose_all_kernel(
    const float* __restrict__ Wq, const float* __restrict__ Wk,
    const float* __restrict__ Wv, const float* __restrict__ Wo,
    __half* __restrict__ Tqkv, __half* __restrict__ Two)
{
    __shared__ float tile[32][33];
    const int bx = blockIdx.x;
    const float* W;
    __half* T;
    int n0, rowbase, Nsrc;
    float mul = 1.f;
    if (bx < 64)      { W = Wq; T = Tqkv; n0 = bx * 32;        rowbase = 0;    Nsrc = DOUT;
                        mul = 0.08838834764831845f; }
    else if (bx < 80) { W = Wk; T = Tqkv; n0 = (bx - 64) * 32; rowbase = 2048; Nsrc = KVDIM; }
    else if (bx < 96) { W = Wv; T = Tqkv; n0 = (bx - 80) * 32; rowbase = 2560; Nsrc = KVDIM; }
    else              { W = Wo; T = Two;  n0 = (bx - 96) * 32; rowbase = 0;    Nsrc = DOUT; }
    const int k0 = blockIdx.y * 32;
    const int tx = threadIdx.x & 31, ty = threadIdx.x >> 5;
    #pragma unroll
    for (int r = ty; r < 32; r += 8)
        tile[r][tx] = W[(size_t)(k0 + r) * Nsrc + n0 + tx];
    __syncthreads();
    #pragma unroll
    for (int r = ty; r < 32; r += 8)
        T[(size_t)(rowbase + n0 + r) * DIN + k0 + tx] = __float2half_rn(tile[tx][r] * mul);
}

// ---------------- HMMA 1-pass GEMM: 4 warps, 64x64 warp tiles, BK=32, 3-stage, swizzled ----------------
#define GBK       32
#define TILE_B    (128 * 64)               // 8192 B
#define STAGE_B   (2 * TILE_B)             // 16384 B (A, B)
#define NSTAGE    3
#define GEMM_SMEM (NSTAGE * STAGE_B)       // 49152 B

#define SWZ(r, ck) ((uint32_t)(r) * 64u + ((uint32_t)((ck) ^ (((r) >> 1) & 3)) << 4))

__global__ __launch_bounds__(128, 2) void mma_gemm_kernel(
    const __half* __restrict__ A, const __half* __restrict__ B,
    float* __restrict__ C, const float* __restrict__ bias,
    __half* __restrict__ q16, __half* __restrict__ k16, __half* __restrict__ v16,
    int N, int K)
{
    extern __shared__ char smem[];
    const uint32_t sb = smem_u32(smem);
    const int tid  = threadIdx.x;
    const int wid  = tid >> 5;
    const int lane = tid & 31;
    const int row0 = blockIdx.y * 128;
    const int col0 = blockIdx.x * 128;
    const int wm   = (wid & 1) * 64;
    const int wn   = (wid >> 1) * 64;

    float acc[4][8][4];
    #pragma unroll
    for (int i = 0; i < 4; i++)
        #pragma unroll
        for (int j = 0; j < 8; j++)
            #pragma unroll
            for (int r = 0; r < 4; r++) acc[i][j][r] = 0.f;

    const int nch = K / GBK;

    auto load_stage = [&](int ch, int stage) {
        const int k0 = ch * GBK;
        const uint32_t sbase = sb + stage * STAGE_B;
        #pragma unroll
        for (int t = 0; t < 8; t++) {
            int idx = tid + t * 128;
            int tensor = idx >> 9;
            int rem = idx & 511;
            int r = rem >> 2;
            int c = rem & 3;
            const __half* gp = (tensor == 0)
                ? A + (size_t)(row0 + r) * K + k0 + c * 8
                : B + (size_t)(col0 + r) * K + k0 + c * 8;
            cp_async16(sbase + tensor * TILE_B + SWZ(r, c), gp);
        }
    };

    load_stage(0, 0); CP_COMMIT();
    load_stage(1, 1); CP_COMMIT();

    int stage = 0;
    for (int ch = 0; ch < nch; ch++) {
        if (ch + 1 < nch) { CP_WAIT(1); } else { CP_WAIT(0); }
        __syncthreads();
        if (ch + 2 < nch) {
            int s2 = stage + 2; if (s2 >= NSTAGE) s2 -= NSTAGE;
            load_stage(ch + 2, s2);
            CP_COMMIT();
        }

        const uint32_t sbase = sb + stage * STAGE_B;
        const uint32_t a_t = sbase;
        const uint32_t b_t = sbase + TILE_B;

        #pragma unroll
        for (int ks = 0; ks < 2; ks++) {
            uint32_t fa[4][4];
            #pragma unroll
            for (int mi = 0; mi < 4; mi++) {
                int r = wm + mi * 16 + (lane & 15);
                int ck = ks * 2 + (lane >> 4);
                ldm_x4(fa[mi][0], fa[mi][1], fa[mi][2], fa[mi][3], a_t + SWZ(r, ck));
            }
            uint32_t fb[8][2];
            #pragma unroll
            for (int p = 0; p < 4; p++) {
                int r = wn + p * 16 + (lane >> 4) * 8 + (lane & 7);
                int ck = ks * 2 + ((lane >> 3) & 1);
                uint32_t r0, r1, r2, r3;
                ldm_x4(r0, r1, r2, r3, b_t + SWZ(r, ck));
                fb[2 * p][0] = r0; fb[2 * p][1] = r1;
                fb[2 * p + 1][0] = r2; fb[2 * p + 1][1] = r3;
            }
            #pragma unroll
            for (int mi = 0; mi < 4; mi++)
                #pragma unroll
                for (int ni = 0; ni < 8; ni++)
                    mma_f16(acc[mi][ni], fa[mi], fb[ni]);
        }
        stage++; if (stage >= NSTAGE) stage -= NSTAGE;
    }

    const int qrow = lane >> 2;
    const int qcol = (lane & 3) * 2;
    if (C != nullptr) {
        #pragma unroll
        for (int mi = 0; mi < 4; mi++)
            #pragma unroll
            for (int ni = 0; ni < 8; ni++) {
                int r = row0 + wm + mi * 16 + qrow;
                int c = col0 + wn + ni * 8 + qcol;
                float b0 = 0.f, b1 = 0.f;
                if (bias != nullptr) { b0 = bias[c]; b1 = bias[c + 1]; }
                *(float2*)(C + (size_t)r * N + c) =
                    make_float2(acc[mi][ni][0] + b0, acc[mi][ni][1] + b1);
                *(float2*)(C + (size_t)(r + 8) * N + c) =
                    make_float2(acc[mi][ni][2] + b0, acc[mi][ni][3] + b1);
            }
    } else {
        __half* dst; int nD, c0;
        if (col0 < DOUT)              { dst = q16; nD = DOUT;  c0 = col0; }
        else if (col0 < DOUT + KVDIM) { dst = k16; nD = KVDIM; c0 = col0 - DOUT; }
        else                          { dst = v16; nD = KVDIM; c0 = col0 - DOUT - KVDIM; }
        #pragma unroll
        for (int mi = 0; mi < 4; mi++)
            #pragma unroll
            for (int ni = 0; ni < 8; ni++) {
                int r = row0 + wm + mi * 16 + qrow;
                int c = c0 + wn + ni * 8 + qcol;
                *(uint32_t*)(dst + (size_t)r * nD + c) =
                    pack_half2(acc[mi][ni][0], acc[mi][ni][1]);
                *(uint32_t*)(dst + (size_t)(r + 8) * nD + c) =
                    pack_half2(acc[mi][ni][2], acc[mi][ni][3]);
            }
    }
}

// ---------------- HMMA fp16 causal GQA flash attention ----------------
// CTA: (b,h) x 64 query rows; 4 warps x 16 rows; key blocks of 64, double-buffered.
// Q is pre-scaled by 1/sqrt(HD) (folded into Wq). Single-sync pipeline.
#define AROWB 136                          // halfs per padded row (272 B)
#define ATILE (64 * AROWB * 2)             // 17408 B
#define ATTN_SMEM (5 * ATILE)              // 87040 B: Q, K0, V0, K1, V1

__global__ __launch_bounds__(128, 2) void attn6_kernel(
    const __half* __restrict__ Q,
    const __half* __restrict__ K16,
    const __half* __restrict__ V16,
    __half* __restrict__ Cx)
{
    extern __shared__ char smem[];
    const uint32_t sb = smem_u32(smem);
    const int tid  = threadIdx.x;
    const int wid  = tid >> 5;
    const int lane = tid & 31;
    const int b = blockIdx.z;
    const int h = blockIdx.y;
    const int g = h >> 2;
    const int qb = gridDim.x - 1 - blockIdx.x;
    const int q0 = qb * 64;
    const int wrow = wid * 16;

    const uint32_t s_q = sb;
    auto s_k = [&](int buf) { return sb + ATILE + buf * 2 * ATILE; };
    auto s_v = [&](int buf) { return sb + 2 * ATILE + buf * 2 * ATILE; };

    #pragma unroll
    for (int t = 0; t < 8; t++) {
        int idx = tid + t * 128;
        int r = idx >> 4;
        int c = idx & 15;
        size_t go = ((size_t)(b * NSEQ + q0 + r) * NH + h) * HD + c * 8;
        cp_async16(s_q + (uint32_t)r * (AROWB * 2) + c * 16, Q + go);
    }

    auto load_kv = [&](int kb, int buf) {
        #pragma unroll
        for (int t = 0; t < 8; t++) {
            int idx = tid + t * 128;
            int r = idx >> 4;
            int c = idx & 15;
            size_t go = ((size_t)(b * NSEQ + kb * 64 + r) * NG + g) * HD + c * 8;
            uint32_t so = (uint32_t)r * (AROWB * 2) + c * 16;
            cp_async16(s_k(buf) + so, K16 + go);
            cp_async16(s_v(buf) + so, V16 + go);
        }
        CP_COMMIT();
    };

    load_kv(0, 0);   // Q rides in this group too

    float m0 = -1e30f, m1 = -1e30f, l0 = 0.f, l1 = 0.f;
    float o[16][4];
    #pragma unroll
    for (int n = 0; n < 16; n++)
        #pragma unroll
        for (int r = 0; r < 4; r++) o[n][r] = 0.f;

    for (int kb = 0; kb <= qb; kb++) {
        const int cur = kb & 1;
        CP_WAIT(0);
        __syncthreads();
        if (kb < qb) load_kv(kb + 1, 1 - cur);

        const uint32_t sk = s_k(cur), sv = s_v(cur);

        float sacc[8][4];
        #pragma unroll
        for (int j = 0; j < 8; j++)
            #pragma unroll
            for (int r = 0; r < 4; r++) sacc[j][r] = 0.f;

        #pragma unroll
        for (int kc = 0; kc < 8; kc++) {
            uint32_t aoff = (uint32_t)(wrow + (lane & 15)) * (AROWB * 2)
                          + kc * 32 + (lane >> 4) * 16;
            uint32_t fa[4];
            ldm_x4(fa[0], fa[1], fa[2], fa[3], s_q + aoff);
            uint32_t fb[8][2];
            #pragma unroll
            for (int p = 0; p < 4; p++) {
                uint32_t boff = (uint32_t)(p * 16 + (lane >> 4) * 8 + (lane & 7)) * (AROWB * 2)
                              + kc * 32 + ((lane >> 3) & 1) * 16;
                uint32_t r0, r1, r2, r3;
                ldm_x4(r0, r1, r2, r3, sk + boff);
                fb[2 * p][0] = r0; fb[2 * p][1] = r1;
                fb[2 * p + 1][0] = r2; fb[2 * p + 1][1] = r3;
            }
            #pragma unroll
            for (int j = 0; j < 8; j++)
                mma_f16(sacc[j], fa, fb[j]);
        }

        // scores are pre-scaled (Wq folded); mask + row stats
        const bool diag = (kb == qb);
        const int qr0 = q0 + wrow + (lane >> 2);
        float mb0 = -1e30f, mb1 = -1e30f;
        #pragma unroll
        for (int j = 0; j < 8; j++) {
            if (diag) {
                int key = kb * 64 + j * 8 + (lane & 3) * 2;
                if (key     > qr0)     sacc[j][0] = -1e30f;
                if (key + 1 > qr0)     sacc[j][1] = -1e30f;
                if (key     > qr0 + 8) sacc[j][2] = -1e30f;
                if (key + 1 > qr0 + 8) sacc[j][3] = -1e30f;
            }
            mb0 = fmaxf(mb0, fmaxf(sacc[j][0], sacc[j][1]));
            mb1 = fmaxf(mb1, fmaxf(sacc[j][2], sacc[j][3]));
        }
        mb0 = fmaxf(mb0, __shfl_xor_sync(0xFFFFFFFFu, mb0, 1));
        mb0 = fmaxf(mb0, __shfl_xor_sync(0xFFFFFFFFu, mb0, 2));
        mb1 = fmaxf(mb1, __shfl_xor_sync(0xFFFFFFFFu, mb1, 1));
        mb1 = fmaxf(mb1, __shfl_xor_sync(0xFFFFFFFFu, mb1, 2));

        float mn0 = fmaxf(m0, mb0), mn1 = fmaxf(m1, mb1);
        float a0 = __expf(m0 - mn0), a1 = __expf(m1 - mn1);
        m0 = mn0; m1 = mn1;

        float s0 = 0.f, s1 = 0.f;
        uint32_t pa[4][4];
        #pragma unroll
        for (int j = 0; j < 8; j++) {
            float p0 = __expf(sacc[j][0] - mn0);
            float p1 = __expf(sacc[j][1] - mn0);
            float p2 = __expf(sacc[j][2] - mn1);
            float p3 = __expf(sacc[j][3] - mn1);
            s0 += p0 + p1;
            s1 += p2 + p3;
            int t = j >> 1, w = (j & 1) * 2;
            pa[t][0 + w] = pack_half2(p0, p1);
            pa[t][1 + w] = pack_half2(p2, p3);
        }
        s0 += __shfl_xor_sync(0xFFFFFFFFu, s0, 1);
        s0 += __shfl_xor_sync(0xFFFFFFFFu, s0, 2);
        s1 += __shfl_xor_sync(0xFFFFFFFFu, s1, 1);
        s1 += __shfl_xor_sync(0xFFFFFFFFu, s1, 2);
        l0 = l0 * a0 + s0;
        l1 = l1 * a1 + s1;

        #pragma unroll
        for (int n = 0; n < 16; n++) {
            o[n][0] *= a0; o[n][1] *= a0;
            o[n][2] *= a1; o[n][3] *= a1;
        }

        #pragma unroll
        for (int np = 0; np < 8; np++) {
            #pragma unroll
            for (int t = 0; t < 4; t++) {
                uint32_t vaddr = (uint32_t)(16 * t + (lane & 7) + ((lane >> 3) & 1) * 8) * (AROWB * 2)
                               + (np * 16 + (lane >> 4) * 8) * 2;
                uint32_t h0, h1, h2, h3;
                ldm_x4t(h0, h1, h2, h3, sv + vaddr);
                uint32_t bh0[2] = {h0, h1}, bh1[2] = {h2, h3};
                mma_f16(o[2 * np],     pa[t], bh0);
                mma_f16(o[2 * np + 1], pa[t], bh1);
            }
        }
    }

    const float inv0 = 1.f / l0, inv1 = 1.f / l1;
    const int r0g = q0 + wrow + (lane >> 2);
    const int r1g = r0g + 8;
    #pragma unroll
    for (int n = 0; n < 16; n++) {
        int d = n * 8 + (lane & 3) * 2;
        size_t off0 = ((size_t)(b * NSEQ + r0g) * NH + h) * HD + d;
        size_t off1 = ((size_t)(b * NSEQ + r1g) * NH + h) * HD + d;
        *(uint32_t*)(Cx + off0) = pack_half2(o[n][0] * inv0, o[n][1] * inv0);
        *(uint32_t*)(Cx + off1) = pack_half2(o[n][2] * inv1, o[n][3] * inv1);
    }
}

// ---------------- launch ----------------
extern "C" void kernel_launch(void* const* d_in, const int* in_sizes, int n_in,
                              void* d_out, int out_size)
{
    const float* x  = (const float*)d_in[0];
    const float* Wq = (const float*)d_in[1];
    const float* Wk = (const float*)d_in[2];
    const float* Wv = (const float*)d_in[3];
    const float* Wo = (const float*)d_in[4];
    const float* bo = (const float*)d_in[5];
    float* out = (float*)d_out;

    __half *q16, *k16, *v16, *x16, *ctx16, *wqkvt, *wot;
    cudaGetSymbolAddress((void**)&q16,   g_q16);
    cudaGetSymbolAddress((void**)&k16,   g_k16);
    cudaGetSymbolAddress((void**)&v16,   g_v16);
    cudaGetSymbolAddress((void**)&x16,   g_x16);
    cudaGetSymbolAddress((void**)&ctx16, g_ctx16);
    cudaGetSymbolAddress((void**)&wqkvt, g_wqkvt);
    cudaGetSymbolAddress((void**)&wot,   g_wot);

    static bool attrs_set = false;
    if (!attrs_set) {
        cudaFuncSetAttribute(mma_gemm_kernel, cudaFuncAttributeMaxDynamicSharedMemorySize,
                             GEMM_SMEM);
        cudaFuncSetAttribute(attn6_kernel, cudaFuncAttributeMaxDynamicSharedMemorySize,
                             ATTN_SMEM);
        attrs_set = true;
    }

    dim3 blk(256);

    // conversions (2 launches)
    round_fp16_kernel<<<(MROWS * DIN / 4 + 255) / 256, blk>>>(x, x16, MROWS * DIN / 4);
    transpose_all_kernel<<<dim3(160, DIN / 32), blk>>>(Wq, Wk, Wv, Wo, wqkvt, wot);

    // fused QKV projection (fp16 outputs, routed by column; Wq pre-scaled)
    mma_gemm_kernel<<<dim3(NQKV / 128, MROWS / 128), dim3(128), GEMM_SMEM>>>(
        x16, wqkvt, nullptr, nullptr, q16, k16, v16, NQKV, DIN);

    // attention (fp16 ctx output)
    attn6_kernel<<<dim3(NSEQ / 64, NH, BSZ), dim3(128), ATTN_SMEM>>>(
        q16, k16, v16, ctx16);

    // output projection (1-pass, fp32 + bias)
    mma_gemm_kernel<<<dim3(DOUT / 128, MROWS / 128), dim3(128), GEMM_SMEM>>>(
        ctx16, wot, out, bo, nullptr, nullptr, nullptr, DOUT, DOUT);
}

// round 15
// speedup vs baseline: 1.5515x; 1.0101x over previous
#include <cuda_runtime.h>
#include <cuda_fp16.h>
#include <cstdint>
#include <cstddef>

// Problem constants
#define BSZ   2
#define NSEQ  2048
#define DIN   2048
#define DOUT  2048
#define NH    16
#define NG    4
#define HD    128
#define MROWS (BSZ * NSEQ)   // 4096
#define KVDIM (NG * HD)      // 512
#define NQKV  (DOUT + 2 * KVDIM)   // 3072

// ---------------- scratch (no allocations allowed) ----------------
__device__ __align__(16) __half g_q16[MROWS * DOUT];
__device__ __align__(16) __half g_k16[MROWS * KVDIM];
__device__ __align__(16) __half g_v16[MROWS * KVDIM];
__device__ __align__(16) __half g_x16[MROWS * DIN];
__device__ __align__(16) __half g_ctx16[MROWS * DOUT];
__device__ __align__(16) __half g_wqkvt[NQKV * DIN];    // [Wq*scale;Wk;Wv]^T
__device__ __align__(16) __half g_wot[DOUT * DOUT];     // Wo^T

// ---------------- helpers ----------------
__device__ __forceinline__ uint32_t smem_u32(const void* p) {
    uint32_t a;
    asm("{ .reg .u64 t; cvta.to.shared.u64 t, %1; cvt.u32.u64 %0, t; }" : "=r"(a) : "l"(p));
    return a;
}
__device__ __forceinline__ void cp_async16(uint32_t saddr, const void* gaddr) {
    asm volatile("cp.async.cg.shared.global [%0], [%1], 16;" :: "r"(saddr), "l"(gaddr));
}
#define CP_COMMIT() asm volatile("cp.async.commit_group;" ::: "memory")
#define CP_WAIT(n)  asm volatile("cp.async.wait_group %0;" :: "n"(n) : "memory")

__device__ __forceinline__ void ldm_x4(uint32_t& r0, uint32_t& r1, uint32_t& r2, uint32_t& r3,
                                       uint32_t addr) {
    asm volatile("ldmatrix.sync.aligned.m8n8.x4.shared.b16 {%0, %1, %2, %3}, [%4];"
                 : "=r"(r0), "=r"(r1), "=r"(r2), "=r"(r3) : "r"(addr));
}
__device__ __forceinline__ void ldm_x4t(uint32_t& r0, uint32_t& r1, uint32_t& r2, uint32_t& r3,
                                        uint32_t addr) {
    asm volatile("ldmatrix.sync.aligned.m8n8.x4.trans.shared.b16 {%0, %1, %2, %3}, [%4];"
                 : "=r"(r0), "=r"(r1), "=r"(r2), "=r"(r3) : "r"(addr));
}
__device__ __forceinline__ void mma_f16(float* d, const uint32_t* a, const uint32_t* b) {
    asm volatile(
        "mma.sync.aligned.m16n8k16.row.col.f32.f16.f16.f32 "
        "{%0, %1, %2, %3}, {%4, %5, %6, %7}, {%8, %9}, {%0, %1, %2, %3};"
        : "+f"(d[0]), "+f"(d[1]), "+f"(d[2]), "+f"(d[3])
        : "r"(a[0]), "r"(a[1]), "r"(a[2]), "r"(a[3]), "r"(b[0]), "r"(b[1]));
}
__device__ __forceinline__ uint32_t pack_half2(float a, float b) {
    __half2 h = __halves2half2(__float2half_rn(a), __float2half_rn(b));
    return *reinterpret_cast<uint32_t*>(&h);
}

// ---------------- conversion kernels ----------------
__global__ __launch_bounds__(256) void round_fp16_kernel(
    const float* __restrict__ in, __half* __restrict__ out, int n4)
{
    int i = blockIdx.x * 256 + threadIdx.x;
    if (i >= n4) return;
    float4 v = ((const float4*)in)[i];
    ((__half2*)out)[2 * i]     = __halves2half2(__float2half_rn(v.x), __float2half_rn(v.y));
    ((__half2*)out)[2 * i + 1] = __halves2half2(__float2half_rn(v.z), __float2half_rn(v.w));
}

// Fused transpose of Wq(*scale)/Wk/Wv/Wo.
__global__ __launch_bounds__(256) void transpose_all_kernel(
    const float* __restrict__ Wq, const float* __restrict__ Wk,
    const float* __restrict__ Wv, const float* __restrict__ Wo,
    __half* __restrict__ Tqkv, __half* __restrict__ Two)
{
    __shared__ float tile[32][33];
    const int bx = blockIdx.x;
    const float* W;
    __half* T;
    int n0, rowbase, Nsrc;
    float mul = 1.f;
    if (bx < 64)      { W = Wq; T = Tqkv; n0 = bx * 32;        rowbase = 0;    Nsrc = DOUT;
                        mul = 0.08838834764831845f; }
    else if (bx < 80) { W = Wk; T = Tqkv; n0 = (bx - 64) * 32; rowbase = 2048; Nsrc = KVDIM; }
    else if (bx < 96) { W = Wv; T = Tqkv; n0 = (bx - 80) * 32; rowbase = 2560; Nsrc = KVDIM; }
    else              { W = Wo; T = Two;  n0 = (bx - 96) * 32; rowbase = 0;    Nsrc = DOUT; }
    const int k0 = blockIdx.y * 32;
    const int tx = threadIdx.x & 31, ty = threadIdx.x >> 5;
    #pragma unroll
    for (int r = ty; r < 32; r += 8)
        tile[r][tx] = W[(size_t)(k0 + r) * Nsrc + n0 + tx];
    __syncthreads();
    #pragma unroll
    for (int r = ty; r < 32; r += 8)
        T[(size_t)(rowbase + n0 + r) * DIN + k0 + tx] = __float2half_rn(tile[tx][r] * mul);
}

// ---------------- HMMA 1-pass GEMM: 4 warps, 64x64 warp tiles, BK=32, 3-stage, swizzled ----------------
#define GBK       32
#define TILE_B    (128 * 64)               // 8192 B
#define STAGE_B   (2 * TILE_B)             // 16384 B (A, B)
#define NSTAGE    3
#define GEMM_SMEM (NSTAGE * STAGE_B)       // 49152 B

#define SWZ(r, ck) ((uint32_t)(r) * 64u + ((uint32_t)((ck) ^ (((r) >> 1) & 3)) << 4))

__global__ __launch_bounds__(128, 2) void mma_gemm_kernel(
    const __half* __restrict__ A, const __half* __restrict__ B,
    float* __restrict__ C, const float* __restrict__ bias,
    __half* __restrict__ q16, __half* __restrict__ k16, __half* __restrict__ v16,
    int N, int K)
{
    extern __shared__ char smem[];
    const uint32_t sb = smem_u32(smem);
    const int tid  = threadIdx.x;
    const int wid  = tid >> 5;
    const int lane = tid & 31;
    const int row0 = blockIdx.y * 128;
    const int col0 = blockIdx.x * 128;
    const int wm   = (wid & 1) * 64;
    const int wn   = (wid >> 1) * 64;

    float acc[4][8][4];
    #pragma unroll
    for (int i = 0; i < 4; i++)
        #pragma unroll
        for (int j = 0; j < 8; j++)
            #pragma unroll
            for (int r = 0; r < 4; r++) acc[i][j][r] = 0.f;

    const int nch = K / GBK;

    auto load_stage = [&](int ch, int stage) {
        const int k0 = ch * GBK;
        const uint32_t sbase = sb + stage * STAGE_B;
        #pragma unroll
        for (int t = 0; t < 8; t++) {
            int idx = tid + t * 128;
            int tensor = idx >> 9;
            int rem = idx & 511;
            int r = rem >> 2;
            int c = rem & 3;
            const __half* gp = (tensor == 0)
                ? A + (size_t)(row0 + r) * K + k0 + c * 8
                : B + (size_t)(col0 + r) * K + k0 + c * 8;
            cp_async16(sbase + tensor * TILE_B + SWZ(r, c), gp);
        }
    };

    load_stage(0, 0); CP_COMMIT();
    load_stage(1, 1); CP_COMMIT();

    int stage = 0;
    for (int ch = 0; ch < nch; ch++) {
        if (ch + 1 < nch) { CP_WAIT(1); } else { CP_WAIT(0); }
        __syncthreads();
        if (ch + 2 < nch) {
            int s2 = stage + 2; if (s2 >= NSTAGE) s2 -= NSTAGE;
            load_stage(ch + 2, s2);
            CP_COMMIT();
        }

        const uint32_t sbase = sb + stage * STAGE_B;
        const uint32_t a_t = sbase;
        const uint32_t b_t = sbase + TILE_B;

        #pragma unroll
        for (int ks = 0; ks < 2; ks++) {
            uint32_t fa[4][4];
            #pragma unroll
            for (int mi = 0; mi < 4; mi++) {
                int r = wm + mi * 16 + (lane & 15);
                int ck = ks * 2 + (lane >> 4);
                ldm_x4(fa[mi][0], fa[mi][1], fa[mi][2], fa[mi][3], a_t + SWZ(r, ck));
            }
            uint32_t fb[8][2];
            #pragma unroll
            for (int p = 0; p < 4; p++) {
                int r = wn + p * 16 + (lane >> 4) * 8 + (lane & 7);
                int ck = ks * 2 + ((lane >> 3) & 1);
                uint32_t r0, r1, r2, r3;
                ldm_x4(r0, r1, r2, r3, b_t + SWZ(r, ck));
                fb[2 * p][0] = r0; fb[2 * p][1] = r1;
                fb[2 * p + 1][0] = r2; fb[2 * p + 1][1] = r3;
            }
            #pragma unroll
            for (int mi = 0; mi < 4; mi++)
                #pragma unroll
                for (int ni = 0; ni < 8; ni++)
                    mma_f16(acc[mi][ni], fa[mi], fb[ni]);
        }
        stage++; if (stage >= NSTAGE) stage -= NSTAGE;
    }

    const int qrow = lane >> 2;
    const int qcol = (lane & 3) * 2;
    if (C != nullptr) {
        #pragma unroll
        for (int mi = 0; mi < 4; mi++)
            #pragma unroll
            for (int ni = 0; ni < 8; ni++) {
                int r = row0 + wm + mi * 16 + qrow;
                int c = col0 + wn + ni * 8 + qcol;
                float b0 = 0.f, b1 = 0.f;
                if (bias != nullptr) { b0 = bias[c]; b1 = bias[c + 1]; }
                *(float2*)(C + (size_t)r * N + c) =
                    make_float2(acc[mi][ni][0] + b0, acc[mi][ni][1] + b1);
                *(float2*)(C + (size_t)(r + 8) * N + c) =
                    make_float2(acc[mi][ni][2] + b0, acc[mi][ni][3] + b1);
            }
    } else {
        __half* dst; int nD, c0;
        if (col0 < DOUT)              { dst = q16; nD = DOUT;  c0 = col0; }
        else if (col0 < DOUT + KVDIM) { dst = k16; nD = KVDIM; c0 = col0 - DOUT; }
        else                          { dst = v16; nD = KVDIM; c0 = col0 - DOUT - KVDIM; }
        #pragma unroll
        for (int mi = 0; mi < 4; mi++)
            #pragma unroll
            for (int ni = 0; ni < 8; ni++) {
                int r = row0 + wm + mi * 16 + qrow;
                int c = c0 + wn + ni * 8 + qcol;
                *(uint32_t*)(dst + (size_t)r * nD + c) =
                    pack_half2(acc[mi][ni][0], acc[mi][ni][1]);
                *(uint32_t*)(dst + (size_t)(r + 8) * nD + c) =
                    pack_half2(acc[mi][ni][2], acc[mi][ni][3]);
            }
    }
}

// ---------------- HMMA fp16 causal GQA flash attention ----------------
// CTA: (b,h) x 64 query rows; 4 warps x 16 rows; key blocks of 64, double-buffered.
// Q pre-scaled (Wq fold); Q fragments register-resident across the key loop.
#define AROWB 136                          // halfs per padded row (272 B)
#define ATILE (64 * AROWB * 2)             // 17408 B
#define ATTN_SMEM (5 * ATILE)              // 87040 B: Q, K0, V0, K1, V1

__global__ __launch_bounds__(128, 2) void attn6_kernel(
    const __half* __restrict__ Q,
    const __half* __restrict__ K16,
    const __half* __restrict__ V16,
    __half* __restrict__ Cx)
{
    extern __shared__ char smem[];
    const uint32_t sb = smem_u32(smem);
    const int tid  = threadIdx.x;
    const int wid  = tid >> 5;
    const int lane = tid & 31;
    const int b = blockIdx.z;
    const int h = blockIdx.y;
    const int g = h >> 2;
    const int qb = gridDim.x - 1 - blockIdx.x;
    const int q0 = qb * 64;
    const int wrow = wid * 16;

    const uint32_t s_q = sb;
    auto s_k = [&](int buf) { return sb + ATILE + buf * 2 * ATILE; };
    auto s_v = [&](int buf) { return sb + 2 * ATILE + buf * 2 * ATILE; };

    #pragma unroll
    for (int t = 0; t < 8; t++) {
        int idx = tid + t * 128;
        int r = idx >> 4;
        int c = idx & 15;
        size_t go = ((size_t)(b * NSEQ + q0 + r) * NH + h) * HD + c * 8;
        cp_async16(s_q + (uint32_t)r * (AROWB * 2) + c * 16, Q + go);
    }

    auto load_kv = [&](int kb, int buf) {
        #pragma unroll
        for (int t = 0; t < 8; t++) {
            int idx = tid + t * 128;
            int r = idx >> 4;
            int c = idx & 15;
            size_t go = ((size_t)(b * NSEQ + kb * 64 + r) * NG + g) * HD + c * 8;
            uint32_t so = (uint32_t)r * (AROWB * 2) + c * 16;
            cp_async16(s_k(buf) + so, K16 + go);
            cp_async16(s_v(buf) + so, V16 + go);
        }
        CP_COMMIT();
    };

    load_kv(0, 0);   // Q rides in this group too

    float m0 = -1e30f, m1 = -1e30f, l0 = 0.f, l1 = 0.f;
    float o[16][4];
    #pragma unroll
    for (int n = 0; n < 16; n++)
        #pragma unroll
        for (int r = 0; r < 4; r++) o[n][r] = 0.f;

    uint32_t faq[8][4];   // Q fragments, loaded once at kb==0

    for (int kb = 0; kb <= qb; kb++) {
        const int cur = kb & 1;
        CP_WAIT(0);
        __syncthreads();
        if (kb == 0) {
            // hoist Q fragments into registers (invariant across key blocks)
            #pragma unroll
            for (int kc = 0; kc < 8; kc++) {
                uint32_t aoff = (uint32_t)(wrow + (lane & 15)) * (AROWB * 2)
                              + kc * 32 + (lane >> 4) * 16;
                ldm_x4(faq[kc][0], faq[kc][1], faq[kc][2], faq[kc][3], s_q + aoff);
            }
        }
        if (kb < qb) load_kv(kb + 1, 1 - cur);

        const uint32_t sk = s_k(cur), sv = s_v(cur);

        float sacc[8][4];
        #pragma unroll
        for (int j = 0; j < 8; j++)
            #pragma unroll
            for (int r = 0; r < 4; r++) sacc[j][r] = 0.f;

        #pragma unroll
        for (int kc = 0; kc < 8; kc++) {
            uint32_t fb[8][2];
            #pragma unroll
            for (int p = 0; p < 4; p++) {
                uint32_t boff = (uint32_t)(p * 16 + (lane >> 4) * 8 + (lane & 7)) * (AROWB * 2)
                              + kc * 32 + ((lane >> 3) & 1) * 16;
                uint32_t r0, r1, r2, r3;
                ldm_x4(r0, r1, r2, r3, sk + boff);
                fb[2 * p][0] = r0; fb[2 * p][1] = r1;
                fb[2 * p + 1][0] = r2; fb[2 * p + 1][1] = r3;
            }
            #pragma unroll
            for (int j = 0; j < 8; j++)
                mma_f16(sacc[j], faq[kc], fb[j]);
        }

        // mask + row stats (scores pre-scaled via Wq fold)
        const bool diag = (kb == qb);
        const int qr0 = q0 + wrow + (lane >> 2);
        float mb0 = -1e30f, mb1 = -1e30f;
        #pragma unroll
        for (int j = 0; j < 8; j++) {
            if (diag) {
                int key = kb * 64 + j * 8 + (lane & 3) * 2;
                if (key     > qr0)     sacc[j][0] = -1e30f;
                if (key + 1 > qr0)     sacc[j][1] = -1e30f;
                if (key     > qr0 + 8) sacc[j][2] = -1e30f;
                if (key + 1 > qr0 + 8) sacc[j][3] = -1e30f;
            }
            mb0 = fmaxf(mb0, fmaxf(sacc[j][0], sacc[j][1]));
            mb1 = fmaxf(mb1, fmaxf(sacc[j][2], sacc[j][3]));
        }
        mb0 = fmaxf(mb0, __shfl_xor_sync(0xFFFFFFFFu, mb0, 1));
        mb0 = fmaxf(mb0, __shfl_xor_sync(0xFFFFFFFFu, mb0, 2));
        mb1 = fmaxf(mb1, __shfl_xor_sync(0xFFFFFFFFu, mb1, 1));
        mb1 = fmaxf(mb1, __shfl_xor_sync(0xFFFFFFFFu, mb1, 2));

        float mn0 = fmaxf(m0, mb0), mn1 = fmaxf(m1, mb1);
        float a0 = __expf(m0 - mn0), a1 = __expf(m1 - mn1);
        m0 = mn0; m1 = mn1;

        float s0 = 0.f, s1 = 0.f;
        uint32_t pa[4][4];
        #pragma unroll
        for (int j = 0; j < 8; j++) {
            float p0 = __expf(sacc[j][0] - mn0);
            float p1 = __expf(sacc[j][1] - mn0);
            float p2 = __expf(sacc[j][2] - mn1);
            float p3 = __expf(sacc[j][3] - mn1);
            s0 += p0 + p1;
            s1 += p2 + p3;
            int t = j >> 1, w = (j & 1) * 2;
            pa[t][0 + w] = pack_half2(p0, p1);
            pa[t][1 + w] = pack_half2(p2, p3);
        }
        s0 += __shfl_xor_sync(0xFFFFFFFFu, s0, 1);
        s0 += __shfl_xor_sync(0xFFFFFFFFu, s0, 2);
        s1 += __shfl_xor_sync(0xFFFFFFFFu, s1, 1);
        s1 += __shfl_xor_sync(0xFFFFFFFFu, s1, 2);
        l0 = l0 * a0 + s0;
        l1 = l1 * a1 + s1;

        #pragma unroll
        for (int n = 0; n < 16; n++) {
            o[n][0] *= a0; o[n][1] *= a0;
            o[n][2] *= a1; o[n][3] *= a1;
        }

        #pragma unroll
        for (int np = 0; np < 8; np++) {
            #pragma unroll
            for (int t = 0; t < 4; t++) {
                uint32_t vaddr = (uint32_t)(16 * t + (lane & 7) + ((lane >> 3) & 1) * 8) * (AROWB * 2)
                               + (np * 16 + (lane >> 4) * 8) * 2;
                uint32_t h0, h1, h2, h3;
                ldm_x4t(h0, h1, h2, h3, sv + vaddr);
                uint32_t bh0[2] = {h0, h1}, bh1[2] = {h2, h3};
                mma_f16(o[2 * np],     pa[t], bh0);
                mma_f16(o[2 * np + 1], pa[t], bh1);
            }
        }
    }

    const float inv0 = 1.f / l0, inv1 = 1.f / l1;
    const int r0g = q0 + wrow + (lane >> 2);
    const int r1g = r0g + 8;
    #pragma unroll
    for (int n = 0; n < 16; n++) {
        int d = n * 8 + (lane & 3) * 2;
        size_t off0 = ((size_t)(b * NSEQ + r0g) * NH + h) * HD + d;
        size_t off1 = ((size_t)(b * NSEQ + r1g) * NH + h) * HD + d;
        *(uint32_t*)(Cx + off0) = pack_half2(o[n][0] * inv0, o[n][1] * inv0);
        *(uint32_t*)(Cx + off1) = pack_half2(o[n][2] * inv1, o[n][3] * inv1);
    }
}

// ---------------- launch ----------------
extern "C" void kernel_launch(void* const* d_in, const int* in_sizes, int n_in,
                              void* d_out, int out_size)
{
    const float* x  = (const float*)d_in[0];
    const float* Wq = (const float*)d_in[1];
    const float* Wk = (const float*)d_in[2];
    const float* Wv = (const float*)d_in[3];
    const float* Wo = (const float*)d_in[4];
    const float* bo = (const float*)d_in[5];
    float* out = (float*)d_out;

    __half *q16, *k16, *v16, *x16, *ctx16, *wqkvt, *wot;
    cudaGetSymbolAddress((void**)&q16,   g_q16);
    cudaGetSymbolAddress((void**)&k16,   g_k16);
    cudaGetSymbolAddress((void**)&v16,   g_v16);
    cudaGetSymbolAddress((void**)&x16,   g_x16);
    cudaGetSymbolAddress((void**)&ctx16, g_ctx16);
    cudaGetSymbolAddress((void**)&wqkvt, g_wqkvt);
    cudaGetSymbolAddress((void**)&wot,   g_wot);

    static bool attrs_set = false;
    if (!attrs_set) {
        cudaFuncSetAttribute(mma_gemm_kernel, cudaFuncAttributeMaxDynamicSharedMemorySize,
                             GEMM_SMEM);
        cudaFuncSetAttribute(attn6_kernel, cudaFuncAttributeMaxDynamicSharedMemorySize,
                             ATTN_SMEM);
        attrs_set = true;
    }

    dim3 blk(256);

    // conversions (2 launches)
    round_fp16_kernel<<<(MROWS * DIN / 4 + 255) / 256, blk>>>(x, x16, MROWS * DIN / 4);
    transpose_all_kernel<<<dim3(160, DIN / 32), blk>>>(Wq, Wk, Wv, Wo, wqkvt, wot);

    // fused QKV projection (fp16 outputs, routed by column; Wq pre-scaled)
    mma_gemm_kernel<<<dim3(NQKV / 128, MROWS / 128), dim3(128), GEMM_SMEM>>>(
        x16, wqkvt, nullptr, nullptr, q16, k16, v16, NQKV, DIN);

    // attention (fp16 ctx output)
    attn6_kernel<<<dim3(NSEQ / 64, NH, BSZ), dim3(128), ATTN_SMEM>>>(
        q16, k16, v16, ctx16);

    // output projection (1-pass, fp32 + bias)
    mma_gemm_kernel<<<dim3(DOUT / 128, MROWS / 128), dim3(128), GEMM_SMEM>>>(
        ctx16, wot, out, bo, nullptr, nullptr, nullptr, DOUT, DOUT);
}

// round 16
// speedup vs baseline: 1.5539x; 1.0015x over previous
#include <cuda_runtime.h>
#include <cuda_fp16.h>
#include <cstdint>
#include <cstddef>

// Problem constants
#define BSZ   2
#define NSEQ  2048
#define DIN   2048
#define DOUT  2048
#define NH    16
#define NG    4
#define HD    128
#define MROWS (BSZ * NSEQ)   // 4096
#define KVDIM (NG * HD)      // 512
#define NQKV  (DOUT + 2 * KVDIM)   // 3072

// ---------------- scratch (no allocations allowed) ----------------
__device__ __align__(16) __half g_q16[MROWS * DOUT];
__device__ __align__(16) __half g_k16[MROWS * KVDIM];
__device__ __align__(16) __half g_v16[MROWS * KVDIM];
__device__ __align__(16) __half g_x16[MROWS * DIN];
__device__ __align__(16) __half g_ctx16[MROWS * DOUT];
__device__ __align__(16) __half g_wqkvt[NQKV * DIN];    // [Wq*scale*log2e;Wk;Wv]^T
__device__ __align__(16) __half g_wot[DOUT * DOUT];     // Wo^T

// ---------------- helpers ----------------
__device__ __forceinline__ uint32_t smem_u32(const void* p) {
    uint32_t a;
    asm("{ .reg .u64 t; cvta.to.shared.u64 t, %1; cvt.u32.u64 %0, t; }" : "=r"(a) : "l"(p));
    return a;
}
__device__ __forceinline__ void cp_async16(uint32_t saddr, const void* gaddr) {
    asm volatile("cp.async.cg.shared.global [%0], [%1], 16;" :: "r"(saddr), "l"(gaddr));
}
#define CP_COMMIT() asm volatile("cp.async.commit_group;" ::: "memory")
#define CP_WAIT(n)  asm volatile("cp.async.wait_group %0;" :: "n"(n) : "memory")

__device__ __forceinline__ void ldm_x4(uint32_t& r0, uint32_t& r1, uint32_t& r2, uint32_t& r3,
                                       uint32_t addr) {
    asm volatile("ldmatrix.sync.aligned.m8n8.x4.shared.b16 {%0, %1, %2, %3}, [%4];"
                 : "=r"(r0), "=r"(r1), "=r"(r2), "=r"(r3) : "r"(addr));
}
__device__ __forceinline__ void ldm_x4t(uint32_t& r0, uint32_t& r1, uint32_t& r2, uint32_t& r3,
                                        uint32_t addr) {
    asm volatile("ldmatrix.sync.aligned.m8n8.x4.trans.shared.b16 {%0, %1, %2, %3}, [%4];"
                 : "=r"(r0), "=r"(r1), "=r"(r2), "=r"(r3) : "r"(addr));
}
__device__ __forceinline__ void mma_f16(float* d, const uint32_t* a, const uint32_t* b) {
    asm volatile(
        "mma.sync.aligned.m16n8k16.row.col.f32.f16.f16.f32 "
        "{%0, %1, %2, %3}, {%4, %5, %6, %7}, {%8, %9}, {%0, %1, %2, %3};"
        : "+f"(d[0]), "+f"(d[1]), "+f"(d[2]), "+f"(d[3])
        : "r"(a[0]), "r"(a[1]), "r"(a[2]), "r"(a[3]), "r"(b[0]), "r"(b[1]));
}
__device__ __forceinline__ uint32_t pack_half2(float a, float b) {
    __half2 h = __halves2half2(__float2half_rn(a), __float2half_rn(b));
    return *reinterpret_cast<uint32_t*>(&h);
}
__device__ __forceinline__ float ex2(float x) {
    float r;
    asm("ex2.approx.ftz.f32 %0, %1;" : "=f"(r) : "f"(x));
    return r;
}

// ---------------- conversion kernels ----------------
__global__ __launch_bounds__(256) void round_fp16_kernel(
    const float* __restrict__ in, __half* __restrict__ out, int n4)
{
    int i = blockIdx.x * 256 + threadIdx.x;
    if (i >= n4) return;
    float4 v = ((const float4*)in)[i];
    ((__half2*)out)[2 * i]     = __halves2half2(__float2half_rn(v.x), __float2half_rn(v.y));
    ((__half2*)out)[2 * i + 1] = __halves2half2(__float2half_rn(v.z), __float2half_rn(v.w));
}

// Fused transpose of Wq(*scale*log2e)/Wk/Wv/Wo.
__global__ __launch_bounds__(256) void transpose_all_kernel(
    const float* __restrict__ Wq, const float* __restrict__ Wk,
    const float* __restrict__ Wv, const float* __restrict__ Wo,
    __half* __restrict__ Tqkv, __half* __restrict__ Two)
{
    __shared__ float tile[32][33];
    const int bx = blockIdx.x;
    const float* W;
    __half* T;
    int n0, rowbase, Nsrc;
    float mul = 1.f;
    if (bx < 64)      { W = Wq; T = Tqkv; n0 = bx * 32;        rowbase = 0;    Nsrc = DOUT;
                        mul = 0.12751879526588722f; }   // (1/sqrt(128)) * log2(e)
    else if (bx < 80) { W = Wk; T = Tqkv; n0 = (bx - 64) * 32; rowbase = 2048; Nsrc = KVDIM; }
    else if (bx < 96) { W = Wv; T = Tqkv; n0 = (bx - 80) * 32; rowbase = 2560; Nsrc = KVDIM; }
    else              { W = Wo; T = Two;  n0 = (bx - 96) * 32; rowbase = 0;    Nsrc = DOUT; }
    const int k0 = blockIdx.y * 32;
    const int tx = threadIdx.x & 31, ty = threadIdx.x >> 5;
    #pragma unroll
    for (int r = ty; r < 32; r += 8)
        tile[r][tx] = W[(size_t)(k0 + r) * Nsrc + n0 + tx];
    __syncthreads();
    #pragma unroll
    for (int r = ty; r < 32; r += 8)
        T[(size_t)(rowbase + n0 + r) * DIN + k0 + tx] = __float2half_rn(tile[tx][r] * mul);
}

// ---------------- HMMA 1-pass GEMM: 4 warps, 64x64 warp tiles, BK=32, 3-stage, swizzled ----------------
#define GBK       32
#define TILE_B    (128 * 64)               // 8192 B
#define STAGE_B   (2 * TILE_B)             // 16384 B (A, B)
#define NSTAGE    3
#define GEMM_SMEM (NSTAGE * STAGE_B)       // 49152 B

#define SWZ(r, ck) ((uint32_t)(r) * 64u + ((uint32_t)((ck) ^ (((r) >> 1) & 3)) << 4))

__global__ __launch_bounds__(128, 2) void mma_gemm_kernel(
    const __half* __restrict__ A, const __half* __restrict__ B,
    float* __restrict__ C, const float* __restrict__ bias,
    __half* __restrict__ q16, __half* __restrict__ k16, __half* __restrict__ v16,
    int N, int K)
{
    extern __shared__ char smem[];
    const uint32_t sb = smem_u32(smem);
    const int tid  = threadIdx.x;
    const int wid  = tid >> 5;
    const int lane = tid & 31;
    const int row0 = blockIdx.y * 128;
    const int col0 = blockIdx.x * 128;
    const int wm   = (wid & 1) * 64;
    const int wn   = (wid >> 1) * 64;

    float acc[4][8][4];
    #pragma unroll
    for (int i = 0; i < 4; i++)
        #pragma unroll
        for (int j = 0; j < 8; j++)
            #pragma unroll
            for (int r = 0; r < 4; r++) acc[i][j][r] = 0.f;

    const int nch = K / GBK;

    auto load_stage = [&](int ch, int stage) {
        const int k0 = ch * GBK;
        const uint32_t sbase = sb + stage * STAGE_B;
        #pragma unroll
        for (int t = 0; t < 8; t++) {
            int idx = tid + t * 128;
            int tensor = idx >> 9;
            int rem = idx & 511;
            int r = rem >> 2;
            int c = rem & 3;
            const __half* gp = (tensor == 0)
                ? A + (size_t)(row0 + r) * K + k0 + c * 8
                : B + (size_t)(col0 + r) * K + k0 + c * 8;
            cp_async16(sbase + tensor * TILE_B + SWZ(r, c), gp);
        }
    };

    load_stage(0, 0); CP_COMMIT();
    load_stage(1, 1); CP_COMMIT();

    int stage = 0;
    for (int ch = 0; ch < nch; ch++) {
        if (ch + 1 < nch) { CP_WAIT(1); } else { CP_WAIT(0); }
        __syncthreads();
        if (ch + 2 < nch) {
            int s2 = stage + 2; if (s2 >= NSTAGE) s2 -= NSTAGE;
            load_stage(ch + 2, s2);
            CP_COMMIT();
        }

        const uint32_t sbase = sb + stage * STAGE_B;
        const uint32_t a_t = sbase;
        const uint32_t b_t = sbase + TILE_B;

        #pragma unroll
        for (int ks = 0; ks < 2; ks++) {
            uint32_t fa[4][4];
            #pragma unroll
            for (int mi = 0; mi < 4; mi++) {
                int r = wm + mi * 16 + (lane & 15);
                int ck = ks * 2 + (lane >> 4);
                ldm_x4(fa[mi][0], fa[mi][1], fa[mi][2], fa[mi][3], a_t + SWZ(r, ck));
            }
            uint32_t fb[8][2];
            #pragma unroll
            for (int p = 0; p < 4; p++) {
                int r = wn + p * 16 + (lane >> 4) * 8 + (lane & 7);
                int ck = ks * 2 + ((lane >> 3) & 1);
                uint32_t r0, r1, r2, r3;
                ldm_x4(r0, r1, r2, r3, b_t + SWZ(r, ck));
                fb[2 * p][0] = r0; fb[2 * p][1] = r1;
                fb[2 * p + 1][0] = r2; fb[2 * p + 1][1] = r3;
            }
            #pragma unroll
            for (int mi = 0; mi < 4; mi++)
                #pragma unroll
                for (int ni = 0; ni < 8; ni++)
                    mma_f16(acc[mi][ni], fa[mi], fb[ni]);
        }
        stage++; if (stage >= NSTAGE) stage -= NSTAGE;
    }

    const int qrow = lane >> 2;
    const int qcol = (lane & 3) * 2;
    if (C != nullptr) {
        #pragma unroll
        for (int mi = 0; mi < 4; mi++)
            #pragma unroll
            for (int ni = 0; ni < 8; ni++) {
                int r = row0 + wm + mi * 16 + qrow;
                int c = col0 + wn + ni * 8 + qcol;
                float b0 = 0.f, b1 = 0.f;
                if (bias != nullptr) { b0 = bias[c]; b1 = bias[c + 1]; }
                *(float2*)(C + (size_t)r * N + c) =
                    make_float2(acc[mi][ni][0] + b0, acc[mi][ni][1] + b1);
                *(float2*)(C + (size_t)(r + 8) * N + c) =
                    make_float2(acc[mi][ni][2] + b0, acc[mi][ni][3] + b1);
            }
    } else {
        __half* dst; int nD, c0;
        if (col0 < DOUT)              { dst = q16; nD = DOUT;  c0 = col0; }
        else if (col0 < DOUT + KVDIM) { dst = k16; nD = KVDIM; c0 = col0 - DOUT; }
        else                          { dst = v16; nD = KVDIM; c0 = col0 - DOUT - KVDIM; }
        #pragma unroll
        for (int mi = 0; mi < 4; mi++)
            #pragma unroll
            for (int ni = 0; ni < 8; ni++) {
                int r = row0 + wm + mi * 16 + qrow;
                int c = c0 + wn + ni * 8 + qcol;
                *(uint32_t*)(dst + (size_t)r * nD + c) =
                    pack_half2(acc[mi][ni][0], acc[mi][ni][1]);
                *(uint32_t*)(dst + (size_t)(r + 8) * nD + c) =
                    pack_half2(acc[mi][ni][2], acc[mi][ni][3]);
            }
    }
}

// ---------------- HMMA fp16 causal GQA flash attention ----------------
// CTA: (b,h) x 64 query rows; 4 warps x 16 rows; key blocks of 64, double-buffered.
// Q pre-scaled by (1/sqrt(HD))*log2(e): softmax in base-2 via ex2.approx.
// Register-resident Q fragments; vote-skipped O rescale.
#define AROWB 136                          // halfs per padded row (272 B)
#define ATILE (64 * AROWB * 2)             // 17408 B
#define ATTN_SMEM (5 * ATILE)              // 87040 B: Q, K0, V0, K1, V1

__global__ __launch_bounds__(128, 2) void attn6_kernel(
    const __half* __restrict__ Q,
    const __half* __restrict__ K16,
    const __half* __restrict__ V16,
    __half* __restrict__ Cx)
{
    extern __shared__ char smem[];
    const uint32_t sb = smem_u32(smem);
    const int tid  = threadIdx.x;
    const int wid  = tid >> 5;
    const int lane = tid & 31;
    const int b = blockIdx.z;
    const int h = blockIdx.y;
    const int g = h >> 2;
    const int qb = gridDim.x - 1 - blockIdx.x;
    const int q0 = qb * 64;
    const int wrow = wid * 16;

    const uint32_t s_q = sb;
    auto s_k = [&](int buf) { return sb + ATILE + buf * 2 * ATILE; };
    auto s_v = [&](int buf) { return sb + 2 * ATILE + buf * 2 * ATILE; };

    #pragma unroll
    for (int t = 0; t < 8; t++) {
        int idx = tid + t * 128;
        int r = idx >> 4;
        int c = idx & 15;
        size_t go = ((size_t)(b * NSEQ + q0 + r) * NH + h) * HD + c * 8;
        cp_async16(s_q + (uint32_t)r * (AROWB * 2) + c * 16, Q + go);
    }

    auto load_kv = [&](int kb, int buf) {
        #pragma unroll
        for (int t = 0; t < 8; t++) {
            int idx = tid + t * 128;
            int r = idx >> 4;
            int c = idx & 15;
            size_t go = ((size_t)(b * NSEQ + kb * 64 + r) * NG + g) * HD + c * 8;
            uint32_t so = (uint32_t)r * (AROWB * 2) + c * 16;
            cp_async16(s_k(buf) + so, K16 + go);
            cp_async16(s_v(buf) + so, V16 + go);
        }
        CP_COMMIT();
    };

    load_kv(0, 0);   // Q rides in this group too

    float m0 = -1e30f, m1 = -1e30f, l0 = 0.f, l1 = 0.f;
    float o[16][4];
    #pragma unroll
    for (int n = 0; n < 16; n++)
        #pragma unroll
        for (int r = 0; r < 4; r++) o[n][r] = 0.f;

    uint32_t faq[8][4];   // Q fragments, loaded once at kb==0

    for (int kb = 0; kb <= qb; kb++) {
        const int cur = kb & 1;
        CP_WAIT(0);
        __syncthreads();
        if (kb == 0) {
            #pragma unroll
            for (int kc = 0; kc < 8; kc++) {
                uint32_t aoff = (uint32_t)(wrow + (lane & 15)) * (AROWB * 2)
                              + kc * 32 + (lane >> 4) * 16;
                ldm_x4(faq[kc][0], faq[kc][1], faq[kc][2], faq[kc][3], s_q + aoff);
            }
        }
        if (kb < qb) load_kv(kb + 1, 1 - cur);

        const uint32_t sk = s_k(cur), sv = s_v(cur);

        float sacc[8][4];
        #pragma unroll
        for (int j = 0; j < 8; j++)
            #pragma unroll
            for (int r = 0; r < 4; r++) sacc[j][r] = 0.f;

        #pragma unroll
        for (int kc = 0; kc < 8; kc++) {
            uint32_t fb[8][2];
            #pragma unroll
            for (int p = 0; p < 4; p++) {
                uint32_t boff = (uint32_t)(p * 16 + (lane >> 4) * 8 + (lane & 7)) * (AROWB * 2)
                              + kc * 32 + ((lane >> 3) & 1) * 16;
                uint32_t r0, r1, r2, r3;
                ldm_x4(r0, r1, r2, r3, sk + boff);
                fb[2 * p][0] = r0; fb[2 * p][1] = r1;
                fb[2 * p + 1][0] = r2; fb[2 * p + 1][1] = r3;
            }
            #pragma unroll
            for (int j = 0; j < 8; j++)
                mma_f16(sacc[j], faq[kc], fb[j]);
        }

        // mask + row stats (scores are in log2 domain, pre-scaled)
        const bool diag = (kb == qb);
        const int qr0 = q0 + wrow + (lane >> 2);
        float mb0 = -1e30f, mb1 = -1e30f;
        #pragma unroll
        for (int j = 0; j < 8; j++) {
            if (diag) {
                int key = kb * 64 + j * 8 + (lane & 3) * 2;
                if (key     > qr0)     sacc[j][0] = -1e30f;
                if (key + 1 > qr0)     sacc[j][1] = -1e30f;
                if (key     > qr0 + 8) sacc[j][2] = -1e30f;
                if (key + 1 > qr0 + 8) sacc[j][3] = -1e30f;
            }
            mb0 = fmaxf(mb0, fmaxf(sacc[j][0], sacc[j][1]));
            mb1 = fmaxf(mb1, fmaxf(sacc[j][2], sacc[j][3]));
        }
        mb0 = fmaxf(mb0, __shfl_xor_sync(0xFFFFFFFFu, mb0, 1));
        mb0 = fmaxf(mb0, __shfl_xor_sync(0xFFFFFFFFu, mb0, 2));
        mb1 = fmaxf(mb1, __shfl_xor_sync(0xFFFFFFFFu, mb1, 1));
        mb1 = fmaxf(mb1, __shfl_xor_sync(0xFFFFFFFFu, mb1, 2));

        const float mn0 = fmaxf(m0, mb0), mn1 = fmaxf(m1, mb1);

        float s0 = 0.f, s1 = 0.f;
        uint32_t pa[4][4];
        #pragma unroll
        for (int j = 0; j < 8; j++) {
            float p0 = ex2(sacc[j][0] - mn0);
            float p1 = ex2(sacc[j][1] - mn0);
            float p2 = ex2(sacc[j][2] - mn1);
            float p3 = ex2(sacc[j][3] - mn1);
            s0 += p0 + p1;
            s1 += p2 + p3;
            int t = j >> 1, w = (j & 1) * 2;
            pa[t][0 + w] = pack_half2(p0, p1);
            pa[t][1 + w] = pack_half2(p2, p3);
        }
        s0 += __shfl_xor_sync(0xFFFFFFFFu, s0, 1);
        s0 += __shfl_xor_sync(0xFFFFFFFFu, s0, 2);
        s1 += __shfl_xor_sync(0xFFFFFFFFu, s1, 1);
        s1 += __shfl_xor_sync(0xFFFFFFFFu, s1, 2);

        // vote-skipped rescale: only pay the O-rescale when some row's max moved
        const bool need = (mn0 > m0) || (mn1 > m1);
        if (__any_sync(0xFFFFFFFFu, need)) {
            float a0 = ex2(m0 - mn0), a1 = ex2(m1 - mn1);
            m0 = mn0; m1 = mn1;
            l0 = l0 * a0 + s0;
            l1 = l1 * a1 + s1;
            #pragma unroll
            for (int n = 0; n < 16; n++) {
                o[n][0] *= a0; o[n][1] *= a0;
                o[n][2] *= a1; o[n][3] *= a1;
            }
        } else {
            l0 += s0;
            l1 += s1;
        }

        #pragma unroll
        for (int np = 0; np < 8; np++) {
            #pragma unroll
            for (int t = 0; t < 4; t++) {
                uint32_t vaddr = (uint32_t)(16 * t + (lane & 7) + ((lane >> 3) & 1) * 8) * (AROWB * 2)
                               + (np * 16 + (lane >> 4) * 8) * 2;
                uint32_t h0, h1, h2, h3;
                ldm_x4t(h0, h1, h2, h3, sv + vaddr);
                uint32_t bh0[2] = {h0, h1}, bh1[2] = {h2, h3};
                mma_f16(o[2 * np],     pa[t], bh0);
                mma_f16(o[2 * np + 1], pa[t], bh1);
            }
        }
    }

    const float inv0 = 1.f / l0, inv1 = 1.f / l1;
    const int r0g = q0 + wrow + (lane >> 2);
    const int r1g = r0g + 8;
    #pragma unroll
    for (int n = 0; n < 16; n++) {
        int d = n * 8 + (lane & 3) * 2;
        size_t off0 = ((size_t)(b * NSEQ + r0g) * NH + h) * HD + d;
        size_t off1 = ((size_t)(b * NSEQ + r1g) * NH + h) * HD + d;
        *(uint32_t*)(Cx + off0) = pack_half2(o[n][0] * inv0, o[n][1] * inv0);
        *(uint32_t*)(Cx + off1) = pack_half2(o[n][2] * inv1, o[n][3] * inv1);
    }
}

// ---------------- launch ----------------
extern "C" void kernel_launch(void* const* d_in, const int* in_sizes, int n_in,
                              void* d_out, int out_size)
{
    const float* x  = (const float*)d_in[0];
    const float* Wq = (const float*)d_in[1];
    const float* Wk = (const float*)d_in[2];
    const float* Wv = (const float*)d_in[3];
    const float* Wo = (const float*)d_in[4];
    const float* bo = (const float*)d_in[5];
    float* out = (float*)d_out;

    __half *q16, *k16, *v16, *x16, *ctx16, *wqkvt, *wot;
    cudaGetSymbolAddress((void**)&q16,   g_q16);
    cudaGetSymbolAddress((void**)&k16,   g_k16);
    cudaGetSymbolAddress((void**)&v16,   g_v16);
    cudaGetSymbolAddress((void**)&x16,   g_x16);
    cudaGetSymbolAddress((void**)&ctx16, g_ctx16);
    cudaGetSymbolAddress((void**)&wqkvt, g_wqkvt);
    cudaGetSymbolAddress((void**)&wot,   g_wot);

    static bool attrs_set = false;
    if (!attrs_set) {
        cudaFuncSetAttribute(mma_gemm_kernel, cudaFuncAttributeMaxDynamicSharedMemorySize,
                             GEMM_SMEM);
        cudaFuncSetAttribute(attn6_kernel, cudaFuncAttributeMaxDynamicSharedMemorySize,
                             ATTN_SMEM);
        attrs_set = true;
    }

    dim3 blk(256);

    // conversions (2 launches)
    round_fp16_kernel<<<(MROWS * DIN / 4 + 255) / 256, blk>>>(x, x16, MROWS * DIN / 4);
    transpose_all_kernel<<<dim3(160, DIN / 32), blk>>>(Wq, Wk, Wv, Wo, wqkvt, wot);

    // fused QKV projection (fp16 outputs, routed by column; Wq pre-scaled by scale*log2e)
    mma_gemm_kernel<<<dim3(NQKV / 128, MROWS / 128), dim3(128), GEMM_SMEM>>>(
        x16, wqkvt, nullptr, nullptr, q16, k16, v16, NQKV, DIN);

    // attention (fp16 ctx output)
    attn6_kernel<<<dim3(NSEQ / 64, NH, BSZ), dim3(128), ATTN_SMEM>>>(
        q16, k16, v16, ctx16);

    // output projection (1-pass, fp32 + bias)
    mma_gemm_kernel<<<dim3(DOUT / 128, MROWS / 128), dim3(128), GEMM_SMEM>>>(
        ctx16, wot, out, bo, nullptr, nullptr, nullptr, DOUT, DOUT);
}

// round 17
// speedup vs baseline: 1.5550x; 1.0008x over previous
#include <cuda_runtime.h>
#include <cuda_fp16.h>
#include <cstdint>
#include <cstddef>

// Problem constants
#define BSZ   2
#define NSEQ  2048
#define DIN   2048
#define DOUT  2048
#define NH    16
#define NG    4
#define HD    128
#define MROWS (BSZ * NSEQ)   // 4096
#define KVDIM (NG * HD)      // 512
#define NQKV  (DOUT + 2 * KVDIM)   // 3072

// ---------------- scratch (no allocations allowed) ----------------
__device__ __align__(16) __half g_q16[MROWS * DOUT];
__device__ __align__(16) __half g_k16[MROWS * KVDIM];
__device__ __align__(16) __half g_v16[MROWS * KVDIM];
__device__ __align__(16) __half g_x16[MROWS * DIN];
__device__ __align__(16) __half g_ctx16[MROWS * DOUT];
__device__ __align__(16) __half g_wqkvt[NQKV * DIN];    // [Wq*scale*log2e;Wk;Wv]^T
__device__ __align__(16) __half g_wot[DOUT * DOUT];     // Wo^T

// ---------------- helpers ----------------
__device__ __forceinline__ uint32_t smem_u32(const void* p) {
    uint32_t a;
    asm("{ .reg .u64 t; cvta.to.shared.u64 t, %1; cvt.u32.u64 %0, t; }" : "=r"(a) : "l"(p));
    return a;
}
__device__ __forceinline__ void cp_async16(uint32_t saddr, const void* gaddr) {
    asm volatile("cp.async.cg.shared.global [%0], [%1], 16;" :: "r"(saddr), "l"(gaddr));
}
#define CP_COMMIT() asm volatile("cp.async.commit_group;" ::: "memory")
#define CP_WAIT(n)  asm volatile("cp.async.wait_group %0;" :: "n"(n) : "memory")

__device__ __forceinline__ void ldm_x4(uint32_t& r0, uint32_t& r1, uint32_t& r2, uint32_t& r3,
                                       uint32_t addr) {
    asm volatile("ldmatrix.sync.aligned.m8n8.x4.shared.b16 {%0, %1, %2, %3}, [%4];"
                 : "=r"(r0), "=r"(r1), "=r"(r2), "=r"(r3) : "r"(addr));
}
__device__ __forceinline__ void ldm_x4t(uint32_t& r0, uint32_t& r1, uint32_t& r2, uint32_t& r3,
                                        uint32_t addr) {
    asm volatile("ldmatrix.sync.aligned.m8n8.x4.trans.shared.b16 {%0, %1, %2, %3}, [%4];"
                 : "=r"(r0), "=r"(r1), "=r"(r2), "=r"(r3) : "r"(addr));
}
__device__ __forceinline__ void mma_f16(float* d, const uint32_t* a, const uint32_t* b) {
    asm volatile(
        "mma.sync.aligned.m16n8k16.row.col.f32.f16.f16.f32 "
        "{%0, %1, %2, %3}, {%4, %5, %6, %7}, {%8, %9}, {%0, %1, %2, %3};"
        : "+f"(d[0]), "+f"(d[1]), "+f"(d[2]), "+f"(d[3])
        : "r"(a[0]), "r"(a[1]), "r"(a[2]), "r"(a[3]), "r"(b[0]), "r"(b[1]));
}
__device__ __forceinline__ uint32_t pack_half2(float a, float b) {
    __half2 h = __halves2half2(__float2half_rn(a), __float2half_rn(b));
    return *reinterpret_cast<uint32_t*>(&h);
}
__device__ __forceinline__ float ex2(float x) {
    float r;
    asm("ex2.approx.ftz.f32 %0, %1;" : "=f"(r) : "f"(x));
    return r;
}
// pack (lo,hi) to half2 and take 2^x on both halves in one MUFU op
__device__ __forceinline__ uint32_t ex2_h2(float lo, float hi) {
    uint32_t h;
    asm("{\n\t.reg .b32 t;\n\tcvt.rn.f16x2.f32 t, %2, %1;\n\tex2.approx.f16x2 %0, t;\n\t}"
        : "=r"(h) : "f"(lo), "f"(hi));
    return h;
}

// ---------------- conversion kernels ----------------
__global__ __launch_bounds__(256) void round_fp16_kernel(
    const float* __restrict__ in, __half* __restrict__ out, int n4)
{
    int i = blockIdx.x * 256 + threadIdx.x;
    if (i >= n4) return;
    float4 v = ((const float4*)in)[i];
    ((__half2*)out)[2 * i]     = __halves2half2(__float2half_rn(v.x), __float2half_rn(v.y));
    ((__half2*)out)[2 * i + 1] = __halves2half2(__float2half_rn(v.z), __float2half_rn(v.w));
}

// Fused transpose of Wq(*scale*log2e)/Wk/Wv/Wo.
__global__ __launch_bounds__(256) void transpose_all_kernel(
    const float* __restrict__ Wq, const float* __restrict__ Wk,
    const float* __restrict__ Wv, const float* __restrict__ Wo,
    __half* __restrict__ Tqkv, __half* __restrict__ Two)
{
    __shared__ float tile[32][33];
    const int bx = blockIdx.x;
    const float* W;
    __half* T;
    int n0, rowbase, Nsrc;
    float mul = 1.f;
    if (bx < 64)      { W = Wq; T = Tqkv; n0 = bx * 32;        rowbase = 0;    Nsrc = DOUT;
                        mul = 0.12751879526588722f; }   // (1/sqrt(128)) * log2(e)
    else if (bx < 80) { W = Wk; T = Tqkv; n0 = (bx - 64) * 32; rowbase = 2048; Nsrc = KVDIM; }
    else if (bx < 96) { W = Wv; T = Tqkv; n0 = (bx - 80) * 32; rowbase = 2560; Nsrc = KVDIM; }
    else              { W = Wo; T = Two;  n0 = (bx - 96) * 32; rowbase = 0;    Nsrc = DOUT; }
    const int k0 = blockIdx.y * 32;
    const int tx = threadIdx.x & 31, ty = threadIdx.x >> 5;
    #pragma unroll
    for (int r = ty; r < 32; r += 8)
        tile[r][tx] = W[(size_t)(k0 + r) * Nsrc + n0 + tx];
    __syncthreads();
    #pragma unroll
    for (int r = ty; r < 32; r += 8)
        T[(size_t)(rowbase + n0 + r) * DIN + k0 + tx] = __float2half_rn(tile[tx][r] * mul);
}

// ---------------- HMMA 1-pass GEMM: 4 warps, 64x64 warp tiles, BK=32, 3-stage, swizzled ----------------
#define GBK       32
#define TILE_B    (128 * 64)               // 8192 B
#define STAGE_B   (2 * TILE_B)             // 16384 B (A, B)
#define NSTAGE    3
#define GEMM_SMEM (NSTAGE * STAGE_B)       // 49152 B

#define SWZ(r, ck) ((uint32_t)(r) * 64u + ((uint32_t)((ck) ^ (((r) >> 1) & 3)) << 4))

__global__ __launch_bounds__(128, 2) void mma_gemm_kernel(
    const __half* __restrict__ A, const __half* __restrict__ B,
    float* __restrict__ C, const float* __restrict__ bias,
    __half* __restrict__ q16, __half* __restrict__ k16, __half* __restrict__ v16,
    int N, int K)
{
    extern __shared__ char smem[];
    const uint32_t sb = smem_u32(smem);
    const int tid  = threadIdx.x;
    const int wid  = tid >> 5;
    const int lane = tid & 31;
    const int row0 = blockIdx.y * 128;
    const int col0 = blockIdx.x * 128;
    const int wm   = (wid & 1) * 64;
    const int wn   = (wid >> 1) * 64;

    float acc[4][8][4];
    #pragma unroll
    for (int i = 0; i < 4; i++)
        #pragma unroll
        for (int j = 0; j < 8; j++)
            #pragma unroll
            for (int r = 0; r < 4; r++) acc[i][j][r] = 0.f;

    const int nch = K / GBK;

    auto load_stage = [&](int ch, int stage) {
        const int k0 = ch * GBK;
        const uint32_t sbase = sb + stage * STAGE_B;
        #pragma unroll
        for (int t = 0; t < 8; t++) {
            int idx = tid + t * 128;
            int tensor = idx >> 9;
            int rem = idx & 511;
            int r = rem >> 2;
            int c = rem & 3;
            const __half* gp = (tensor == 0)
                ? A + (size_t)(row0 + r) * K + k0 + c * 8
                : B + (size_t)(col0 + r) * K + k0 + c * 8;
            cp_async16(sbase + tensor * TILE_B + SWZ(r, c), gp);
        }
    };

    load_stage(0, 0); CP_COMMIT();
    load_stage(1, 1); CP_COMMIT();

    int stage = 0;
    for (int ch = 0; ch < nch; ch++) {
        if (ch + 1 < nch) { CP_WAIT(1); } else { CP_WAIT(0); }
        __syncthreads();
        if (ch + 2 < nch) {
            int s2 = stage + 2; if (s2 >= NSTAGE) s2 -= NSTAGE;
            load_stage(ch + 2, s2);
            CP_COMMIT();
        }

        const uint32_t sbase = sb + stage * STAGE_B;
        const uint32_t a_t = sbase;
        const uint32_t b_t = sbase + TILE_B;

        #pragma unroll
        for (int ks = 0; ks < 2; ks++) {
            uint32_t fa[4][4];
            #pragma unroll
            for (int mi = 0; mi < 4; mi++) {
                int r = wm + mi * 16 + (lane & 15);
                int ck = ks * 2 + (lane >> 4);
                ldm_x4(fa[mi][0], fa[mi][1], fa[mi][2], fa[mi][3], a_t + SWZ(r, ck));
            }
            uint32_t fb[8][2];
            #pragma unroll
            for (int p = 0; p < 4; p++) {
                int r = wn + p * 16 + (lane >> 4) * 8 + (lane & 7);
                int ck = ks * 2 + ((lane >> 3) & 1);
                uint32_t r0, r1, r2, r3;
                ldm_x4(r0, r1, r2, r3, b_t + SWZ(r, ck));
                fb[2 * p][0] = r0; fb[2 * p][1] = r1;
                fb[2 * p + 1][0] = r2; fb[2 * p + 1][1] = r3;
            }
            #pragma unroll
            for (int mi = 0; mi < 4; mi++)
                #pragma unroll
                for (int ni = 0; ni < 8; ni++)
                    mma_f16(acc[mi][ni], fa[mi], fb[ni]);
        }
        stage++; if (stage >= NSTAGE) stage -= NSTAGE;
    }

    const int qrow = lane >> 2;
    const int qcol = (lane & 3) * 2;
    if (C != nullptr) {
        #pragma unroll
        for (int mi = 0; mi < 4; mi++)
            #pragma unroll
            for (int ni = 0; ni < 8; ni++) {
                int r = row0 + wm + mi * 16 + qrow;
                int c = col0 + wn + ni * 8 + qcol;
                float b0 = 0.f, b1 = 0.f;
                if (bias != nullptr) { b0 = bias[c]; b1 = bias[c + 1]; }
                *(float2*)(C + (size_t)r * N + c) =
                    make_float2(acc[mi][ni][0] + b0, acc[mi][ni][1] + b1);
                *(float2*)(C + (size_t)(r + 8) * N + c) =
                    make_float2(acc[mi][ni][2] + b0, acc[mi][ni][3] + b1);
            }
    } else {
        __half* dst; int nD, c0;
        if (col0 < DOUT)              { dst = q16; nD = DOUT;  c0 = col0; }
        else if (col0 < DOUT + KVDIM) { dst = k16; nD = KVDIM; c0 = col0 - DOUT; }
        else                          { dst = v16; nD = KVDIM; c0 = col0 - DOUT - KVDIM; }
        #pragma unroll
        for (int mi = 0; mi < 4; mi++)
            #pragma unroll
            for (int ni = 0; ni < 8; ni++) {
                int r = row0 + wm + mi * 16 + qrow;
                int c = c0 + wn + ni * 8 + qcol;
                *(uint32_t*)(dst + (size_t)r * nD + c) =
                    pack_half2(acc[mi][ni][0], acc[mi][ni][1]);
                *(uint32_t*)(dst + (size_t)(r + 8) * nD + c) =
                    pack_half2(acc[mi][ni][2], acc[mi][ni][3]);
            }
    }
}

// ---------------- HMMA fp16 causal GQA flash attention ----------------
// CTA: (b,h) x 64 query rows; 4 warps x 16 rows; key blocks of 64, double-buffered.
// Q pre-scaled by (1/sqrt(HD))*log2(e): base-2 softmax, f16x2 MUFU exp,
// register-resident Q fragments, vote-skipped rescale, deferred l reduction.
#define AROWB 136                          // halfs per padded row (272 B)
#define ATILE (64 * AROWB * 2)             // 17408 B
#define ATTN_SMEM (5 * ATILE)              // 87040 B: Q, K0, V0, K1, V1

__global__ __launch_bounds__(128, 2) void attn6_kernel(
    const __half* __restrict__ Q,
    const __half* __restrict__ K16,
    const __half* __restrict__ V16,
    __half* __restrict__ Cx)
{
    extern __shared__ char smem[];
    const uint32_t sb = smem_u32(smem);
    const int tid  = threadIdx.x;
    const int wid  = tid >> 5;
    const int lane = tid & 31;
    const int b = blockIdx.z;
    const int h = blockIdx.y;
    const int g = h >> 2;
    const int qb = gridDim.x - 1 - blockIdx.x;
    const int q0 = qb * 64;
    const int wrow = wid * 16;

    const uint32_t s_q = sb;
    auto s_k = [&](int buf) { return sb + ATILE + buf * 2 * ATILE; };
    auto s_v = [&](int buf) { return sb + 2 * ATILE + buf * 2 * ATILE; };

    #pragma unroll
    for (int t = 0; t < 8; t++) {
        int idx = tid + t * 128;
        int r = idx >> 4;
        int c = idx & 15;
        size_t go = ((size_t)(b * NSEQ + q0 + r) * NH + h) * HD + c * 8;
        cp_async16(s_q + (uint32_t)r * (AROWB * 2) + c * 16, Q + go);
    }

    auto load_kv = [&](int kb, int buf) {
        #pragma unroll
        for (int t = 0; t < 8; t++) {
            int idx = tid + t * 128;
            int r = idx >> 4;
            int c = idx & 15;
            size_t go = ((size_t)(b * NSEQ + kb * 64 + r) * NG + g) * HD + c * 8;
            uint32_t so = (uint32_t)r * (AROWB * 2) + c * 16;
            cp_async16(s_k(buf) + so, K16 + go);
            cp_async16(s_v(buf) + so, V16 + go);
        }
        CP_COMMIT();
    };

    load_kv(0, 0);   // Q rides in this group too

    float m0 = -1e30f, m1 = -1e30f;
    float l0 = 0.f, l1 = 0.f;          // PER-LANE partial sums (quad-reduced at end)
    float o[16][4];
    #pragma unroll
    for (int n = 0; n < 16; n++)
        #pragma unroll
        for (int r = 0; r < 4; r++) o[n][r] = 0.f;

    uint32_t faq[8][4];   // Q fragments, loaded once at kb==0

    for (int kb = 0; kb <= qb; kb++) {
        const int cur = kb & 1;
        CP_WAIT(0);
        __syncthreads();
        if (kb == 0) {
            #pragma unroll
            for (int kc = 0; kc < 8; kc++) {
                uint32_t aoff = (uint32_t)(wrow + (lane & 15)) * (AROWB * 2)
                              + kc * 32 + (lane >> 4) * 16;
                ldm_x4(faq[kc][0], faq[kc][1], faq[kc][2], faq[kc][3], s_q + aoff);
            }
        }
        if (kb < qb) load_kv(kb + 1, 1 - cur);

        const uint32_t sk = s_k(cur), sv = s_v(cur);

        float sacc[8][4];
        #pragma unroll
        for (int j = 0; j < 8; j++)
            #pragma unroll
            for (int r = 0; r < 4; r++) sacc[j][r] = 0.f;

        #pragma unroll
        for (int kc = 0; kc < 8; kc++) {
            uint32_t fb[8][2];
            #pragma unroll
            for (int p = 0; p < 4; p++) {
                uint32_t boff = (uint32_t)(p * 16 + (lane >> 4) * 8 + (lane & 7)) * (AROWB * 2)
                              + kc * 32 + ((lane >> 3) & 1) * 16;
                uint32_t r0, r1, r2, r3;
                ldm_x4(r0, r1, r2, r3, sk + boff);
                fb[2 * p][0] = r0; fb[2 * p][1] = r1;
                fb[2 * p + 1][0] = r2; fb[2 * p + 1][1] = r3;
            }
            #pragma unroll
            for (int j = 0; j < 8; j++)
                mma_f16(sacc[j], faq[kc], fb[j]);
        }

        // mask + row stats (scores in log2 domain, pre-scaled)
        const bool diag = (kb == qb);
        const int qr0 = q0 + wrow + (lane >> 2);
        float mb0 = -1e30f, mb1 = -1e30f;
        #pragma unroll
        for (int j = 0; j < 8; j++) {
            if (diag) {
                int key = kb * 64 + j * 8 + (lane & 3) * 2;
                if (key     > qr0)     sacc[j][0] = -1e30f;
                if (key + 1 > qr0)     sacc[j][1] = -1e30f;
                if (key     > qr0 + 8) sacc[j][2] = -1e30f;
                if (key + 1 > qr0 + 8) sacc[j][3] = -1e30f;
            }
            mb0 = fmaxf(mb0, fmaxf(sacc[j][0], sacc[j][1]));
            mb1 = fmaxf(mb1, fmaxf(sacc[j][2], sacc[j][3]));
        }
        mb0 = fmaxf(mb0, __shfl_xor_sync(0xFFFFFFFFu, mb0, 1));
        mb0 = fmaxf(mb0, __shfl_xor_sync(0xFFFFFFFFu, mb0, 2));
        mb1 = fmaxf(mb1, __shfl_xor_sync(0xFFFFFFFFu, mb1, 1));
        mb1 = fmaxf(mb1, __shfl_xor_sync(0xFFFFFFFFu, mb1, 2));

        const float mn0 = fmaxf(m0, mb0), mn1 = fmaxf(m1, mb1);

        // exp via f16x2 MUFU (packs P fragments directly); per-lane partial sums
        float s0 = 0.f, s1 = 0.f;
        uint32_t pa[4][4];
        #pragma unroll
        for (int j = 0; j < 8; j++) {
            uint32_t p01 = ex2_h2(sacc[j][0] - mn0, sacc[j][1] - mn0);
            uint32_t p23 = ex2_h2(sacc[j][2] - mn1, sacc[j][3] - mn1);
            int t = j >> 1, w = (j & 1) * 2;
            pa[t][0 + w] = p01;
            pa[t][1 + w] = p23;
            float2 f01 = __half22float2(*reinterpret_cast<__half2*>(&p01));
            float2 f23 = __half22float2(*reinterpret_cast<__half2*>(&p23));
            s0 += f01.x + f01.y;
            s1 += f23.x + f23.y;
        }

        // vote-skipped rescale
        const bool need = (mn0 > m0) || (mn1 > m1);
        if (__any_sync(0xFFFFFFFFu, need)) {
            float a0 = ex2(m0 - mn0), a1 = ex2(m1 - mn1);
            m0 = mn0; m1 = mn1;
            l0 = l0 * a0 + s0;
            l1 = l1 * a1 + s1;
            #pragma unroll
            for (int n = 0; n < 16; n++) {
                o[n][0] *= a0; o[n][1] *= a0;
                o[n][2] *= a1; o[n][3] *= a1;
            }
        } else {
            l0 += s0;
            l1 += s1;
        }

        #pragma unroll
        for (int np = 0; np < 8; np++) {
            #pragma unroll
            for (int t = 0; t < 4; t++) {
                uint32_t vaddr = (uint32_t)(16 * t + (lane & 7) + ((lane >> 3) & 1) * 8) * (AROWB * 2)
                               + (np * 16 + (lane >> 4) * 8) * 2;
                uint32_t h0, h1, h2, h3;
                ldm_x4t(h0, h1, h2, h3, sv + vaddr);
                uint32_t bh0[2] = {h0, h1}, bh1[2] = {h2, h3};
                mma_f16(o[2 * np],     pa[t], bh0);
                mma_f16(o[2 * np + 1], pa[t], bh1);
            }
        }
    }

    // deferred l quad-reduction (once, instead of per block)
    l0 += __shfl_xor_sync(0xFFFFFFFFu, l0, 1);
    l0 += __shfl_xor_sync(0xFFFFFFFFu, l0, 2);
    l1 += __shfl_xor_sync(0xFFFFFFFFu, l1, 1);
    l1 += __shfl_xor_sync(0xFFFFFFFFu, l1, 2);

    const float inv0 = 1.f / l0, inv1 = 1.f / l1;
    const int r0g = q0 + wrow + (lane >> 2);
    const int r1g = r0g + 8;
    #pragma unroll
    for (int n = 0; n < 16; n++) {
        int d = n * 8 + (lane & 3) * 2;
        size_t off0 = ((size_t)(b * NSEQ + r0g) * NH + h) * HD + d;
        size_t off1 = ((size_t)(b * NSEQ + r1g) * NH + h) * HD + d;
        *(uint32_t*)(Cx + off0) = pack_half2(o[n][0] * inv0, o[n][1] * inv0);
        *(uint32_t*)(Cx + off1) = pack_half2(o[n][2] * inv1, o[n][3] * inv1);
    }
}

// ---------------- launch ----------------
extern "C" void kernel_launch(void* const* d_in, const int* in_sizes, int n_in,
                              void* d_out, int out_size)
{
    const float* x  = (const float*)d_in[0];
    const float* Wq = (const float*)d_in[1];
    const float* Wk = (const float*)d_in[2];
    const float* Wv = (const float*)d_in[3];
    const float* Wo = (const float*)d_in[4];
    const float* bo = (const float*)d_in[5];
    float* out = (float*)d_out;

    __half *q16, *k16, *v16, *x16, *ctx16, *wqkvt, *wot;
    cudaGetSymbolAddress((void**)&q16,   g_q16);
    cudaGetSymbolAddress((void**)&k16,   g_k16);
    cudaGetSymbolAddress((void**)&v16,   g_v16);
    cudaGetSymbolAddress((void**)&x16,   g_x16);
    cudaGetSymbolAddress((void**)&ctx16, g_ctx16);
    cudaGetSymbolAddress((void**)&wqkvt, g_wqkvt);
    cudaGetSymbolAddress((void**)&wot,   g_wot);

    static bool attrs_set = false;
    if (!attrs_set) {
        cudaFuncSetAttribute(mma_gemm_kernel, cudaFuncAttributeMaxDynamicSharedMemorySize,
                             GEMM_SMEM);
        cudaFuncSetAttribute(attn6_kernel, cudaFuncAttributeMaxDynamicSharedMemorySize,
                             ATTN_SMEM);
        attrs_set = true;
    }

    dim3 blk(256);

    // conversions (2 launches)
    round_fp16_kernel<<<(MROWS * DIN / 4 + 255) / 256, blk>>>(x, x16, MROWS * DIN / 4);
    transpose_all_kernel<<<dim3(160, DIN / 32), blk>>>(Wq, Wk, Wv, Wo, wqkvt, wot);

    // fused QKV projection (fp16 outputs, routed by column; Wq pre-scaled by scale*log2e)
    mma_gemm_kernel<<<dim3(NQKV / 128, MROWS / 128), dim3(128), GEMM_SMEM>>>(
        x16, wqkvt, nullptr, nullptr, q16, k16, v16, NQKV, DIN);

    // attention (fp16 ctx output)
    attn6_kernel<<<dim3(NSEQ / 64, NH, BSZ), dim3(128), ATTN_SMEM>>>(
        q16, k16, v16, ctx16);

    // output projection (1-pass, fp32 + bias)
    mma_gemm_kernel<<<dim3(DOUT / 128, MROWS / 128), dim3(128), GEMM_SMEM>>>(
        ctx16, wot, out, bo, nullptr, nullptr, nullptr, DOUT, DOUT);
}